// round 12
// baseline (speedup 1.0000x reference)
#include <cuda_runtime.h>
#include <cstdint>

#define IN_F  4096
#define OUT_F 4096
#define NTOK  8192
#define RANK  64

// ---------------- scratch (static device globals; no allocation) ----------------
__device__ float g_X  [(size_t)NTOK * IN_F];    // fwht'd, scaled, tf32-rounded input
__device__ float g_W  [(size_t)OUT_F * IN_F];   // dequantized codebook weights (tf32-rounded)
__device__ float g_Z  [(size_t)NTOK * OUT_F];   // x @ W^T
__device__ float g_ABX[(size_t)NTOK * OUT_F];   // (x B^T) A^T
__device__ float g_XB [NTOK * RANK];            // x @ B^T (tf32-rounded)
__device__ float g_XBp[4 * NTOK * RANK];        // split-K partials for XB
__device__ float g_AQ [OUT_F * RANK];           // tf32-rounded A
__device__ float g_C1 [IN_F];                   // SU / scaleWH

// ---------------- helpers ----------------
__device__ __forceinline__ float tf32r(float f) {
    uint32_t u;
    asm("cvt.rna.tf32.f32 %0, %1;" : "=r"(u) : "f"(f));
    return __uint_as_float(u);
}

#define BFLY(a, b) do { float _u = (a); float _v = (b); (a) = _u + _v; (b) = _u - _v; } while (0)

__device__ __forceinline__ void h8(float e[8]) {
    BFLY(e[0], e[1]); BFLY(e[2], e[3]); BFLY(e[4], e[5]); BFLY(e[6], e[7]);
    BFLY(e[0], e[2]); BFLY(e[1], e[3]); BFLY(e[4], e[6]); BFLY(e[5], e[7]);
    BFLY(e[0], e[4]); BFLY(e[1], e[5]); BFLY(e[2], e[6]); BFLY(e[3], e[7]);
}

// ---------------- tiny prep kernels ----------------
__global__ void c1_kernel(const float* __restrict__ SU, const float* __restrict__ sWH) {
    int i = blockIdx.x * 256 + threadIdx.x;
    if (i < IN_F) g_C1[i] = SU[i] / sWH[i];
}

__global__ void round_a_kernel(const float* __restrict__ A) {
    int i = blockIdx.x * 256 + threadIdx.x;
    if (i < OUT_F * RANK) g_AQ[i] = tf32r(A[i]);
}

// ---------------- dequant: W[m][k] = cb[Q[m][k/8]][k%8], tf32-rounded ----------------
__global__ void dequant_kernel(const int* __restrict__ Q, const float* __restrict__ cb) {
    int i = blockIdx.x * 256 + threadIdx.x;            // 0 .. 4096*512
    if (i >= OUT_F * (IN_F / 8)) return;
    int q = Q[i];
    const float4* c = reinterpret_cast<const float4*>(cb) + ((size_t)q << 1);
    float4 v0 = c[0], v1 = c[1];
    float4 r0, r1;
    r0.x = tf32r(v0.x); r0.y = tf32r(v0.y); r0.z = tf32r(v0.z); r0.w = tf32r(v0.w);
    r1.x = tf32r(v1.x); r1.y = tf32r(v1.y); r1.z = tf32r(v1.z); r1.w = tf32r(v1.w);
    float4* w = reinterpret_cast<float4*>(g_W) + ((size_t)i << 1);
    w[0] = r0; w[1] = r1;
}

// ---------------- FWHT pre: X = fwht(input * C1) / 64, tf32-rounded ----------------
__global__ void __launch_bounds__(512) fwht_pre(const float* __restrict__ in) {
    __shared__ float s[4608];
    int row = blockIdx.x;
    int t = threadIdx.x;
    const float* src = in + (size_t)row * IN_F;
    float e[8];

#pragma unroll
    for (int i = 0; i < 8; i++) { int idx = t + (i << 9); e[i] = src[idx] * g_C1[idx]; }
    h8(e);
#pragma unroll
    for (int i = 0; i < 8; i++) { int idx = t + (i << 9); s[idx + (idx >> 3)] = e[i]; }
    __syncthreads();
    {
        int lo = t & 63, hi = t >> 6;
#pragma unroll
        for (int i = 0; i < 8; i++) { int idx = lo + (i << 6) + (hi << 9); e[i] = s[idx + (idx >> 3)]; }
        h8(e);
#pragma unroll
        for (int i = 0; i < 8; i++) { int idx = lo + (i << 6) + (hi << 9); s[idx + (idx >> 3)] = e[i]; }
    }
    __syncthreads();
    {
        int lo = t & 7, hi = t >> 3;
#pragma unroll
        for (int i = 0; i < 8; i++) { int idx = lo + (i << 3) + (hi << 6); e[i] = s[idx + (idx >> 3)]; }
        h8(e);
#pragma unroll
        for (int i = 0; i < 8; i++) { int idx = lo + (i << 3) + (hi << 6); s[idx + (idx >> 3)] = e[i]; }
    }
    __syncthreads();
    {
#pragma unroll
        for (int i = 0; i < 8; i++) { int idx = (t << 3) + i; e[i] = s[idx + (idx >> 3)]; }
        h8(e);
        float4 o0, o1;
        o0.x = tf32r(e[0] * 0.015625f); o0.y = tf32r(e[1] * 0.015625f);
        o0.z = tf32r(e[2] * 0.015625f); o0.w = tf32r(e[3] * 0.015625f);
        o1.x = tf32r(e[4] * 0.015625f); o1.y = tf32r(e[5] * 0.015625f);
        o1.z = tf32r(e[6] * 0.015625f); o1.w = tf32r(e[7] * 0.015625f);
        float4* dst = reinterpret_cast<float4*>(g_X + (size_t)row * IN_F + (t << 3));
        dst[0] = o0; dst[1] = o1;
    }
}

// ---------------- FWHT post + epilogue ----------------
__global__ void __launch_bounds__(512) fwht_post(const float* __restrict__ SV,
                                                 const float* __restrict__ bias,
                                                 float* __restrict__ out) {
    __shared__ float s[4608];
    int row = blockIdx.x;
    int t = threadIdx.x;
    const float* src = g_Z + (size_t)row * OUT_F;
    float e[8];

#pragma unroll
    for (int i = 0; i < 8; i++) { int idx = t + (i << 9); e[i] = src[idx]; }
    h8(e);
#pragma unroll
    for (int i = 0; i < 8; i++) { int idx = t + (i << 9); s[idx + (idx >> 3)] = e[i]; }
    __syncthreads();
    {
        int lo = t & 63, hi = t >> 6;
#pragma unroll
        for (int i = 0; i < 8; i++) { int idx = lo + (i << 6) + (hi << 9); e[i] = s[idx + (idx >> 3)]; }
        h8(e);
#pragma unroll
        for (int i = 0; i < 8; i++) { int idx = lo + (i << 6) + (hi << 9); s[idx + (idx >> 3)] = e[i]; }
    }
    __syncthreads();
    {
        int lo = t & 7, hi = t >> 3;
#pragma unroll
        for (int i = 0; i < 8; i++) { int idx = lo + (i << 3) + (hi << 6); e[i] = s[idx + (idx >> 3)]; }
        h8(e);
#pragma unroll
        for (int i = 0; i < 8; i++) { int idx = lo + (i << 3) + (hi << 6); s[idx + (idx >> 3)] = e[i]; }
    }
    __syncthreads();
    {
#pragma unroll
        for (int i = 0; i < 8; i++) { int idx = (t << 3) + i; e[i] = s[idx + (idx >> 3)]; }
        h8(e);
        int c0 = t << 3;
        const float4* abx = reinterpret_cast<const float4*>(g_ABX + (size_t)row * OUT_F + c0);
        const float4* sv  = reinterpret_cast<const float4*>(SV + c0);
        const float4* bs  = reinterpret_cast<const float4*>(bias + c0);
        float4 a0 = abx[0], a1 = abx[1];
        float4 s0 = sv[0],  s1 = sv[1];
        float4 b0 = bs[0],  b1 = bs[1];
        float4 o0, o1;
        o0.x = (e[0] * 0.015625f + a0.x) * s0.x + b0.x;
        o0.y = (e[1] * 0.015625f + a0.y) * s0.y + b0.y;
        o0.z = (e[2] * 0.015625f + a0.z) * s0.z + b0.z;
        o0.w = (e[3] * 0.015625f + a0.w) * s0.w + b0.w;
        o1.x = (e[4] * 0.015625f + a1.x) * s1.x + b1.x;
        o1.y = (e[5] * 0.015625f + a1.y) * s1.y + b1.y;
        o1.z = (e[6] * 0.015625f + a1.z) * s1.z + b1.z;
        o1.w = (e[7] * 0.015625f + a1.w) * s1.w + b1.w;
        float4* dst = reinterpret_cast<float4*>(out + (size_t)row * OUT_F + c0);
        dst[0] = o0; dst[1] = o1;
    }
}

// ---------------- XB = X @ B^T, split-K SIMT ----------------
__global__ void __launch_bounds__(256) xb_partial(const float* __restrict__ B) {
    __shared__ float Xs[256][33];
    __shared__ float Bs[64][33];
    int bm = blockIdx.x;
    int ks = blockIdx.y;
    int tid = threadIdx.x;
    int ty = tid >> 3, tx = tid & 7;
    float acc[8][8];
#pragma unroll
    for (int i = 0; i < 8; i++)
#pragma unroll
        for (int j = 0; j < 8; j++) acc[i][j] = 0.f;

    int kbase = ks << 10;
    const float* Xg = g_X + (size_t)(bm * 256) * IN_F + kbase;
    const float* Bg = B + kbase;

    for (int kc = 0; kc < 1024; kc += 32) {
#pragma unroll
        for (int i = 0; i < 8; i++) {
            int f4 = tid + (i << 8);
            int r = f4 >> 3, c4 = (f4 & 7) << 2;
            float4 v = *reinterpret_cast<const float4*>(Xg + (size_t)r * IN_F + kc + c4);
            Xs[r][c4] = v.x; Xs[r][c4 + 1] = v.y; Xs[r][c4 + 2] = v.z; Xs[r][c4 + 3] = v.w;
        }
#pragma unroll
        for (int i = 0; i < 2; i++) {
            int f4 = tid + (i << 8);
            int r = f4 >> 3, c4 = (f4 & 7) << 2;
            float4 v = *reinterpret_cast<const float4*>(Bg + (size_t)r * IN_F + kc + c4);
            Bs[r][c4] = v.x; Bs[r][c4 + 1] = v.y; Bs[r][c4 + 2] = v.z; Bs[r][c4 + 3] = v.w;
        }
        __syncthreads();
#pragma unroll 4
        for (int k = 0; k < 32; k++) {
            float xr[8], br[8];
#pragma unroll
            for (int j = 0; j < 8; j++) xr[j] = Xs[ty * 8 + j][k];
#pragma unroll
            for (int j = 0; j < 8; j++) br[j] = Bs[tx * 8 + j][k];
#pragma unroll
            for (int jr = 0; jr < 8; jr++)
#pragma unroll
                for (int jc = 0; jc < 8; jc++) acc[jr][jc] += xr[jr] * br[jc];
        }
        __syncthreads();
    }
    float* dst = g_XBp + (size_t)ks * (NTOK * RANK) + (size_t)(bm * 256) * RANK;
#pragma unroll
    for (int jr = 0; jr < 8; jr++)
#pragma unroll
        for (int jc = 0; jc < 8; jc++)
            dst[(ty * 8 + jr) * RANK + tx * 8 + jc] = acc[jr][jc];
}

__global__ void xb_reduce() {
    int i = blockIdx.x * 256 + threadIdx.x;
    const int S = NTOK * RANK;
    float s = g_XBp[i] + g_XBp[i + S] + g_XBp[i + 2 * S] + g_XBp[i + 3 * S];
    g_XB[i] = tf32r(s);
}

// ---------------- shared HMMA helpers ----------------
__device__ __forceinline__ void mma_tf32(float* c, const uint32_t* a, const uint32_t* b) {
    asm volatile(
        "mma.sync.aligned.m16n8k8.row.col.f32.tf32.tf32.f32 "
        "{%0,%1,%2,%3}, {%4,%5,%6,%7}, {%8,%9}, {%0,%1,%2,%3};\n"
        : "+f"(c[0]), "+f"(c[1]), "+f"(c[2]), "+f"(c[3])
        : "r"(a[0]), "r"(a[1]), "r"(a[2]), "r"(a[3]), "r"(b[0]), "r"(b[1]));
}

__device__ __forceinline__ void cp16(uint32_t s, const void* g) {
    asm volatile("cp.async.cg.shared.global [%0], [%1], 16;\n" :: "r"(s), "l"(g) : "memory");
}

__device__ __forceinline__ void ldsm4(uint32_t& r0, uint32_t& r1, uint32_t& r2, uint32_t& r3,
                                      uint32_t addr) {
    asm volatile("ldmatrix.sync.aligned.m8n8.x4.shared.b16 {%0,%1,%2,%3}, [%4];"
                 : "=r"(r0), "=r"(r1), "=r"(r2), "=r"(r3) : "r"(addr));
}

// ---------------- small HMMA tf32 GEMM (ABX, K=64): 128x128 tiles ----------------
__device__ __forceinline__ void load_tile(const float* g, int ldg, uint32_t sbase, int tid) {
    int r = tid >> 3;
    int c4 = (tid & 7) << 2;
#pragma unroll
    for (int i = 0; i < 4; i++) {
        int row = r + (i << 5);
        cp16(sbase + (uint32_t)(row * 36 + c4) * 4u, g + (size_t)row * ldg + c4);
    }
}

#define GEMM_TB (128 * 36)
#define GEMM_SMEM (4 * GEMM_TB * 4)

__global__ void __launch_bounds__(256, 2) gemm_nt(const float* __restrict__ A,
                                                  const float* __restrict__ Bm,
                                                  float* __restrict__ C, int K) {
    extern __shared__ float sm[];
    uint32_t sA = (uint32_t)__cvta_generic_to_shared(sm);
    uint32_t sB = sA + 2u * GEMM_TB * 4u;
    int tid = threadIdx.x;
    const float* Ag = A + (size_t)(blockIdx.y * 128) * K;
    const float* Bg = Bm + (size_t)(blockIdx.x * 128) * K;
    int KIT = K >> 5;

    load_tile(Ag, K, sA, tid);
    load_tile(Bg, K, sB, tid);
    asm volatile("cp.async.commit_group;\n" ::: "memory");

    int lane = tid & 31, wid = tid >> 5;
    int g = lane >> 2, tg = lane & 3;
    int wm = (wid & 1) << 6;
    int wn = (wid >> 1) << 5;

    float acc[4][4][4];
#pragma unroll
    for (int a = 0; a < 4; a++)
#pragma unroll
        for (int b = 0; b < 4; b++)
#pragma unroll
            for (int c = 0; c < 4; c++) acc[a][b][c] = 0.f;

    const float* As = sm;
    const float* Bs = sm + 2 * GEMM_TB;

    for (int it = 0; it < KIT; it++) {
        if (it + 1 < KIT) {
            uint32_t nb = ((it + 1) & 1) ? (uint32_t)(GEMM_TB * 4) : 0u;
            load_tile(Ag + (it + 1) * 32, K, sA + nb, tid);
            load_tile(Bg + (it + 1) * 32, K, sB + nb, tid);
            asm volatile("cp.async.commit_group;\n" ::: "memory");
            asm volatile("cp.async.wait_group 1;\n" ::: "memory");
        } else {
            asm volatile("cp.async.wait_group 0;\n" ::: "memory");
        }
        __syncthreads();
        const float* Ac = As + (it & 1) * GEMM_TB;
        const float* Bc = Bs + (it & 1) * GEMM_TB;
#pragma unroll
        for (int ksu = 0; ksu < 4; ksu++) {
            int kc = ksu << 3;
            uint32_t af[4][4], bf[4][2];
#pragma unroll
            for (int mf = 0; mf < 4; mf++) {
                int r0 = wm + (mf << 4) + g;
                af[mf][0] = __float_as_uint(Ac[r0 * 36 + kc + tg]);
                af[mf][1] = __float_as_uint(Ac[(r0 + 8) * 36 + kc + tg]);
                af[mf][2] = __float_as_uint(Ac[r0 * 36 + kc + tg + 4]);
                af[mf][3] = __float_as_uint(Ac[(r0 + 8) * 36 + kc + tg + 4]);
            }
#pragma unroll
            for (int nf = 0; nf < 4; nf++) {
                int n0 = wn + (nf << 3) + g;
                bf[nf][0] = __float_as_uint(Bc[n0 * 36 + kc + tg]);
                bf[nf][1] = __float_as_uint(Bc[n0 * 36 + kc + tg + 4]);
            }
#pragma unroll
            for (int mf = 0; mf < 4; mf++)
#pragma unroll
                for (int nf = 0; nf < 4; nf++)
                    mma_tf32(acc[mf][nf], af[mf], bf[nf]);
        }
        __syncthreads();
    }

    int row0 = (blockIdx.y << 7) + wm + g;
    int col0 = (blockIdx.x << 7) + wn + (tg << 1);
#pragma unroll
    for (int mf = 0; mf < 4; mf++) {
#pragma unroll
        for (int nf = 0; nf < 4; nf++) {
            size_t r = (size_t)(row0 + (mf << 4));
            int c = col0 + (nf << 3);
            float2 v0 = make_float2(acc[mf][nf][0], acc[mf][nf][1]);
            float2 v1 = make_float2(acc[mf][nf][2], acc[mf][nf][3]);
            *reinterpret_cast<float2*>(C + r * 4096 + c) = v0;
            *reinterpret_cast<float2*>(C + (r + 8) * 4096 + c) = v1;
        }
    }
}

// =================================================================================
// Big HMMA tf32 GEMM: Z[8192,4096] = X @ W^T
// CTA tile 128(M) x 256(N) x 32(K), 256 threads = 8 warps (2m x 4n), warp tile
// 64x64 (16 FLOP/smem-byte), 3-stage circular cp.async ring, one barrier/iter,
// 1 CTA/SM with 8 warps (2/SMSP) -> latency hiding that R10's 4-warp CTA lacked.
// =================================================================================
#define Z3_AF   (128 * 36)                 // A stage floats (18432 B)
#define Z3_BF   (256 * 36)                 // B stage floats (36864 B)
#define Z3_STG  (Z3_AF + Z3_BF)            // 13824 floats = 55296 B per stage
#define Z3_SMEM (3 * Z3_STG * 4)           // 165888 B
#define Z3_KIT  128

__device__ __forceinline__ void z3_load(uint32_t sb, int buf, int it,
                                        const float* Ag, const float* Bg, int tid) {
    int k0 = it << 5;
    uint32_t sA = sb + (uint32_t)buf * (Z3_STG * 4);
    uint32_t sB = sA + Z3_AF * 4;
#pragma unroll
    for (int i = 0; i < 4; i++) {           // A: 1024 float4 over 256 threads
        int idx = tid + (i << 8);
        int r = idx >> 3, c4 = (idx & 7) << 2;
        cp16(sA + (uint32_t)(r * 36 + c4) * 4u, Ag + (size_t)r * IN_F + k0 + c4);
    }
#pragma unroll
    for (int i = 0; i < 8; i++) {           // B: 2048 float4
        int idx = tid + (i << 8);
        int r = idx >> 3, c4 = (idx & 7) << 2;
        cp16(sB + (uint32_t)(r * 36 + c4) * 4u, Bg + (size_t)r * IN_F + k0 + c4);
    }
    asm volatile("cp.async.commit_group;\n" ::: "memory");
}

__global__ void __launch_bounds__(256, 1) zgemm_big(const float* __restrict__ Xg,
                                                    const float* __restrict__ Wg,
                                                    float* __restrict__ Zg) {
    extern __shared__ float sm[];
    uint32_t sb = (uint32_t)__cvta_generic_to_shared(sm);
    int tid = threadIdx.x;
    int lane = tid & 31, wid = tid >> 5;   // 8 warps
    int g = lane >> 2, tg = lane & 3;
    int wm = (wid & 1) << 6;        // 2 warps in m -> 128
    int wn = (wid >> 1) << 6;       // 4 warps in n -> 256 (64 cols each)

    const float* Ag = Xg + (size_t)blockIdx.y * 128 * IN_F;
    const float* Bg = Wg + (size_t)blockIdx.x * 256 * IN_F;

    // ldmatrix per-lane offsets (bytes, within a stage tile)
    uint32_t aoff = ((uint32_t)(wm + (((lane >> 3) & 1) << 3) + (lane & 7)) * 36u
                     + (uint32_t)((lane >> 4) << 2)) * 4u;
    uint32_t boff = ((uint32_t)(wn + ((lane >> 4) << 3) + (lane & 7)) * 36u
                     + (uint32_t)(((lane >> 3) & 1) << 2)) * 4u;

    // prologue: tiles 0 and 1
    z3_load(sb, 0, 0, Ag, Bg, tid);
    z3_load(sb, 1, 1, Ag, Bg, tid);

    float acc[4][8][4];                    // 64x64 warp tile: 4 m-frags x 8 n-frags
#pragma unroll
    for (int a = 0; a < 4; a++)
#pragma unroll
        for (int b = 0; b < 8; b++)
#pragma unroll
            for (int c = 0; c < 4; c++) acc[a][b][c] = 0.f;

    for (int it = 0; it < Z3_KIT; it++) {
        int b = it % 3;
        if (it == Z3_KIT - 1) asm volatile("cp.async.wait_group 0;\n" ::: "memory");
        else                  asm volatile("cp.async.wait_group 1;\n" ::: "memory");
        __syncthreads();   // all warps done computing iter it-1 -> slot (it+2)%3 free

        if (it + 2 < Z3_KIT) z3_load(sb, (it + 2) % 3, it + 2, Ag, Bg, tid);

        uint32_t sAb = sb + (uint32_t)b * (Z3_STG * 4) + aoff;
        uint32_t sBb = sb + (uint32_t)b * (Z3_STG * 4) + Z3_AF * 4 + boff;
#pragma unroll
        for (int ksu = 0; ksu < 4; ksu++) {
            uint32_t af[4][4], bf[4][4];
#pragma unroll
            for (int mf = 0; mf < 4; mf++)
                ldsm4(af[mf][0], af[mf][1], af[mf][2], af[mf][3],
                      sAb + (uint32_t)(mf * 2304 + ksu * 32));   // 16*36*4=2304
#pragma unroll
            for (int nfp = 0; nfp < 4; nfp++)
                ldsm4(bf[nfp][0], bf[nfp][1], bf[nfp][2], bf[nfp][3],
                      sBb + (uint32_t)(nfp * 2304 + ksu * 32));
#pragma unroll
            for (int mf = 0; mf < 4; mf++)
#pragma unroll
                for (int nf = 0; nf < 8; nf++)
                    mma_tf32(acc[mf][nf], af[mf], &bf[nf >> 1][(nf & 1) << 1]);
        }
    }

    int row0 = (blockIdx.y << 7) + wm + g;
    int col0 = (blockIdx.x << 8) + wn + (tg << 1);
#pragma unroll
    for (int mf = 0; mf < 4; mf++) {
#pragma unroll
        for (int nf = 0; nf < 8; nf++) {
            size_t r = (size_t)(row0 + (mf << 4));
            int c = col0 + (nf << 3);
            float2 v0 = make_float2(acc[mf][nf][0], acc[mf][nf][1]);
            float2 v1 = make_float2(acc[mf][nf][2], acc[mf][nf][3]);
            *reinterpret_cast<float2*>(Zg + r * 4096 + c) = v0;
            *reinterpret_cast<float2*>(Zg + (r + 8) * 4096 + c) = v1;
        }
    }
}

// ---------------- launch ----------------
extern "C" void kernel_launch(void* const* d_in, const int* in_sizes, int n_in,
                              void* d_out, int out_size) {
    const float* input   = (const float*)d_in[0];
    const int*   Qidxs   = (const int*)d_in[1];
    const float* cb      = (const float*)d_in[2];
    const float* SU      = (const float*)d_in[3];
    const float* SV      = (const float*)d_in[4];
    const float* A       = (const float*)d_in[5];
    const float* B       = (const float*)d_in[6];
    const float* scaleWH = (const float*)d_in[7];
    const float* bias    = (const float*)d_in[8];
    float* out = (float*)d_out;

    static bool attr_done = false;
    if (!attr_done) {
        bool ok1 = cudaFuncSetAttribute(gemm_nt, cudaFuncAttributeMaxDynamicSharedMemorySize,
                                        GEMM_SMEM) == cudaSuccess;
        bool ok2 = cudaFuncSetAttribute(zgemm_big, cudaFuncAttributeMaxDynamicSharedMemorySize,
                                        Z3_SMEM) == cudaSuccess;
        if (ok1 && ok2) attr_done = true;
    }

    static float *X = nullptr, *W = nullptr, *Z = nullptr, *ABX = nullptr,
                 *XB = nullptr, *AQ = nullptr;
    if (!X) {
        cudaGetSymbolAddress((void**)&X,   g_X);
        cudaGetSymbolAddress((void**)&W,   g_W);
        cudaGetSymbolAddress((void**)&Z,   g_Z);
        cudaGetSymbolAddress((void**)&ABX, g_ABX);
        cudaGetSymbolAddress((void**)&XB,  g_XB);
        cudaGetSymbolAddress((void**)&AQ,  g_AQ);
    }

    c1_kernel<<<16, 256>>>(SU, scaleWH);                                     // 1
    fwht_pre<<<NTOK, 512>>>(input);                                          // 2
    dequant_kernel<<<(OUT_F * (IN_F / 8)) / 256, 256>>>(Qidxs, cb);          // 3
    zgemm_big<<<dim3(16, 64), 256, Z3_SMEM>>>(X, W, Z);                      // 4
    round_a_kernel<<<(OUT_F * RANK) / 256, 256>>>(A);                        // 5
    xb_partial<<<dim3(32, 4), 256>>>(B);                                     // 6
    xb_reduce<<<(NTOK * RANK) / 256, 256>>>();                               // 7
    gemm_nt<<<dim3(32, 64), 256, GEMM_SMEM>>>(XB, AQ, ABX, RANK);            // 8
    fwht_post<<<NTOK, 512>>>(SV, bias, out);                                 // 9
}

// round 13
// speedup vs baseline: 1.0581x; 1.0581x over previous
#include <cuda_runtime.h>
#include <cstdint>

#define IN_F  4096
#define OUT_F 4096
#define NTOK  8192
#define RANK  64

// ---------------- scratch (static device globals; no allocation) ----------------
__device__ float g_X  [(size_t)NTOK * IN_F];    // fwht'd, scaled, tf32-rounded input
__device__ float g_W  [(size_t)OUT_F * IN_F];   // dequantized codebook weights (tf32-rounded)
__device__ float g_Z  [(size_t)NTOK * OUT_F];   // x @ W^T
__device__ float g_ABX[(size_t)NTOK * OUT_F];   // (x B^T) A^T
__device__ float g_XB [NTOK * RANK];            // x @ B^T (tf32-rounded)
__device__ float g_XBp[4 * NTOK * RANK];        // split-K partials for XB
__device__ float g_AQ [OUT_F * RANK];           // tf32-rounded A
__device__ float g_C1 [IN_F];                   // SU / scaleWH

// ---------------- helpers ----------------
__device__ __forceinline__ float tf32r(float f) {
    uint32_t u;
    asm("cvt.rna.tf32.f32 %0, %1;" : "=r"(u) : "f"(f));
    return __uint_as_float(u);
}

#define BFLY(a, b) do { float _u = (a); float _v = (b); (a) = _u + _v; (b) = _u - _v; } while (0)

__device__ __forceinline__ void h8(float e[8]) {
    BFLY(e[0], e[1]); BFLY(e[2], e[3]); BFLY(e[4], e[5]); BFLY(e[6], e[7]);
    BFLY(e[0], e[2]); BFLY(e[1], e[3]); BFLY(e[4], e[6]); BFLY(e[5], e[7]);
    BFLY(e[0], e[4]); BFLY(e[1], e[5]); BFLY(e[2], e[6]); BFLY(e[3], e[7]);
}

// ---------------- tiny prep kernels ----------------
__global__ void c1_kernel(const float* __restrict__ SU, const float* __restrict__ sWH) {
    int i = blockIdx.x * 256 + threadIdx.x;
    if (i < IN_F) g_C1[i] = SU[i] / sWH[i];
}

__global__ void round_a_kernel(const float* __restrict__ A) {
    int i = blockIdx.x * 256 + threadIdx.x;
    if (i < OUT_F * RANK) g_AQ[i] = tf32r(A[i]);
}

// ---------------- dequant: W[m][k] = cb[Q[m][k/8]][k%8], tf32-rounded ----------------
__global__ void dequant_kernel(const int* __restrict__ Q, const float* __restrict__ cb) {
    int i = blockIdx.x * 256 + threadIdx.x;            // 0 .. 4096*512
    if (i >= OUT_F * (IN_F / 8)) return;
    int q = Q[i];
    const float4* c = reinterpret_cast<const float4*>(cb) + ((size_t)q << 1);
    float4 v0 = c[0], v1 = c[1];
    float4 r0, r1;
    r0.x = tf32r(v0.x); r0.y = tf32r(v0.y); r0.z = tf32r(v0.z); r0.w = tf32r(v0.w);
    r1.x = tf32r(v1.x); r1.y = tf32r(v1.y); r1.z = tf32r(v1.z); r1.w = tf32r(v1.w);
    float4* w = reinterpret_cast<float4*>(g_W) + ((size_t)i << 1);
    w[0] = r0; w[1] = r1;
}

// ---------------- FWHT pre: X = fwht(input * C1) / 64, tf32-rounded ----------------
__global__ void __launch_bounds__(512) fwht_pre(const float* __restrict__ in) {
    __shared__ float s[4608];
    int row = blockIdx.x;
    int t = threadIdx.x;
    const float* src = in + (size_t)row * IN_F;
    float e[8];

#pragma unroll
    for (int i = 0; i < 8; i++) { int idx = t + (i << 9); e[i] = src[idx] * g_C1[idx]; }
    h8(e);
#pragma unroll
    for (int i = 0; i < 8; i++) { int idx = t + (i << 9); s[idx + (idx >> 3)] = e[i]; }
    __syncthreads();
    {
        int lo = t & 63, hi = t >> 6;
#pragma unroll
        for (int i = 0; i < 8; i++) { int idx = lo + (i << 6) + (hi << 9); e[i] = s[idx + (idx >> 3)]; }
        h8(e);
#pragma unroll
        for (int i = 0; i < 8; i++) { int idx = lo + (i << 6) + (hi << 9); s[idx + (idx >> 3)] = e[i]; }
    }
    __syncthreads();
    {
        int lo = t & 7, hi = t >> 3;
#pragma unroll
        for (int i = 0; i < 8; i++) { int idx = lo + (i << 3) + (hi << 6); e[i] = s[idx + (idx >> 3)]; }
        h8(e);
#pragma unroll
        for (int i = 0; i < 8; i++) { int idx = lo + (i << 3) + (hi << 6); s[idx + (idx >> 3)] = e[i]; }
    }
    __syncthreads();
    {
#pragma unroll
        for (int i = 0; i < 8; i++) { int idx = (t << 3) + i; e[i] = s[idx + (idx >> 3)]; }
        h8(e);
        float4 o0, o1;
        o0.x = tf32r(e[0] * 0.015625f); o0.y = tf32r(e[1] * 0.015625f);
        o0.z = tf32r(e[2] * 0.015625f); o0.w = tf32r(e[3] * 0.015625f);
        o1.x = tf32r(e[4] * 0.015625f); o1.y = tf32r(e[5] * 0.015625f);
        o1.z = tf32r(e[6] * 0.015625f); o1.w = tf32r(e[7] * 0.015625f);
        float4* dst = reinterpret_cast<float4*>(g_X + (size_t)row * IN_F + (t << 3));
        dst[0] = o0; dst[1] = o1;
    }
}

// ---------------- FWHT post + epilogue ----------------
__global__ void __launch_bounds__(512) fwht_post(const float* __restrict__ SV,
                                                 const float* __restrict__ bias,
                                                 float* __restrict__ out) {
    __shared__ float s[4608];
    int row = blockIdx.x;
    int t = threadIdx.x;
    const float* src = g_Z + (size_t)row * OUT_F;
    float e[8];

#pragma unroll
    for (int i = 0; i < 8; i++) { int idx = t + (i << 9); e[i] = src[idx]; }
    h8(e);
#pragma unroll
    for (int i = 0; i < 8; i++) { int idx = t + (i << 9); s[idx + (idx >> 3)] = e[i]; }
    __syncthreads();
    {
        int lo = t & 63, hi = t >> 6;
#pragma unroll
        for (int i = 0; i < 8; i++) { int idx = lo + (i << 6) + (hi << 9); e[i] = s[idx + (idx >> 3)]; }
        h8(e);
#pragma unroll
        for (int i = 0; i < 8; i++) { int idx = lo + (i << 6) + (hi << 9); s[idx + (idx >> 3)] = e[i]; }
    }
    __syncthreads();
    {
        int lo = t & 7, hi = t >> 3;
#pragma unroll
        for (int i = 0; i < 8; i++) { int idx = lo + (i << 3) + (hi << 6); e[i] = s[idx + (idx >> 3)]; }
        h8(e);
#pragma unroll
        for (int i = 0; i < 8; i++) { int idx = lo + (i << 3) + (hi << 6); s[idx + (idx >> 3)] = e[i]; }
    }
    __syncthreads();
    {
#pragma unroll
        for (int i = 0; i < 8; i++) { int idx = (t << 3) + i; e[i] = s[idx + (idx >> 3)]; }
        h8(e);
        int c0 = t << 3;
        const float4* abx = reinterpret_cast<const float4*>(g_ABX + (size_t)row * OUT_F + c0);
        const float4* sv  = reinterpret_cast<const float4*>(SV + c0);
        const float4* bs  = reinterpret_cast<const float4*>(bias + c0);
        float4 a0 = abx[0], a1 = abx[1];
        float4 s0 = sv[0],  s1 = sv[1];
        float4 b0 = bs[0],  b1 = bs[1];
        float4 o0, o1;
        o0.x = (e[0] * 0.015625f + a0.x) * s0.x + b0.x;
        o0.y = (e[1] * 0.015625f + a0.y) * s0.y + b0.y;
        o0.z = (e[2] * 0.015625f + a0.z) * s0.z + b0.z;
        o0.w = (e[3] * 0.015625f + a0.w) * s0.w + b0.w;
        o1.x = (e[4] * 0.015625f + a1.x) * s1.x + b1.x;
        o1.y = (e[5] * 0.015625f + a1.y) * s1.y + b1.y;
        o1.z = (e[6] * 0.015625f + a1.z) * s1.z + b1.z;
        o1.w = (e[7] * 0.015625f + a1.w) * s1.w + b1.w;
        float4* dst = reinterpret_cast<float4*>(out + (size_t)row * OUT_F + c0);
        dst[0] = o0; dst[1] = o1;
    }
}

// ---------------- XB = X @ B^T, split-K SIMT ----------------
__global__ void __launch_bounds__(256) xb_partial(const float* __restrict__ B) {
    __shared__ float Xs[256][33];
    __shared__ float Bs[64][33];
    int bm = blockIdx.x;
    int ks = blockIdx.y;
    int tid = threadIdx.x;
    int ty = tid >> 3, tx = tid & 7;
    float acc[8][8];
#pragma unroll
    for (int i = 0; i < 8; i++)
#pragma unroll
        for (int j = 0; j < 8; j++) acc[i][j] = 0.f;

    int kbase = ks << 10;
    const float* Xg = g_X + (size_t)(bm * 256) * IN_F + kbase;
    const float* Bg = B + kbase;

    for (int kc = 0; kc < 1024; kc += 32) {
#pragma unroll
        for (int i = 0; i < 8; i++) {
            int f4 = tid + (i << 8);
            int r = f4 >> 3, c4 = (f4 & 7) << 2;
            float4 v = *reinterpret_cast<const float4*>(Xg + (size_t)r * IN_F + kc + c4);
            Xs[r][c4] = v.x; Xs[r][c4 + 1] = v.y; Xs[r][c4 + 2] = v.z; Xs[r][c4 + 3] = v.w;
        }
#pragma unroll
        for (int i = 0; i < 2; i++) {
            int f4 = tid + (i << 8);
            int r = f4 >> 3, c4 = (f4 & 7) << 2;
            float4 v = *reinterpret_cast<const float4*>(Bg + (size_t)r * IN_F + kc + c4);
            Bs[r][c4] = v.x; Bs[r][c4 + 1] = v.y; Bs[r][c4 + 2] = v.z; Bs[r][c4 + 3] = v.w;
        }
        __syncthreads();
#pragma unroll 4
        for (int k = 0; k < 32; k++) {
            float xr[8], br[8];
#pragma unroll
            for (int j = 0; j < 8; j++) xr[j] = Xs[ty * 8 + j][k];
#pragma unroll
            for (int j = 0; j < 8; j++) br[j] = Bs[tx * 8 + j][k];
#pragma unroll
            for (int jr = 0; jr < 8; jr++)
#pragma unroll
                for (int jc = 0; jc < 8; jc++) acc[jr][jc] += xr[jr] * br[jc];
        }
        __syncthreads();
    }
    float* dst = g_XBp + (size_t)ks * (NTOK * RANK) + (size_t)(bm * 256) * RANK;
#pragma unroll
    for (int jr = 0; jr < 8; jr++)
#pragma unroll
        for (int jc = 0; jc < 8; jc++)
            dst[(ty * 8 + jr) * RANK + tx * 8 + jc] = acc[jr][jc];
}

__global__ void xb_reduce() {
    int i = blockIdx.x * 256 + threadIdx.x;
    const int S = NTOK * RANK;
    float s = g_XBp[i] + g_XBp[i + S] + g_XBp[i + 2 * S] + g_XBp[i + 3 * S];
    g_XB[i] = tf32r(s);
}

// ---------------- shared HMMA helpers ----------------
__device__ __forceinline__ void mma_tf32(float* c, const uint32_t* a, const uint32_t* b) {
    asm volatile(
        "mma.sync.aligned.m16n8k8.row.col.f32.tf32.tf32.f32 "
        "{%0,%1,%2,%3}, {%4,%5,%6,%7}, {%8,%9}, {%0,%1,%2,%3};\n"
        : "+f"(c[0]), "+f"(c[1]), "+f"(c[2]), "+f"(c[3])
        : "r"(a[0]), "r"(a[1]), "r"(a[2]), "r"(a[3]), "r"(b[0]), "r"(b[1]));
}

__device__ __forceinline__ void cp16(uint32_t s, const void* g) {
    asm volatile("cp.async.cg.shared.global [%0], [%1], 16;\n" :: "r"(s), "l"(g) : "memory");
}

__device__ __forceinline__ void ldsm4(uint32_t& r0, uint32_t& r1, uint32_t& r2, uint32_t& r3,
                                      uint32_t addr) {
    asm volatile("ldmatrix.sync.aligned.m8n8.x4.shared.b16 {%0,%1,%2,%3}, [%4];"
                 : "=r"(r0), "=r"(r1), "=r"(r2), "=r"(r3) : "r"(addr));
}

// ---------------- small HMMA tf32 GEMM (ABX, K=64): 128x128 tiles ----------------
__device__ __forceinline__ void load_tile(const float* g, int ldg, uint32_t sbase, int tid) {
    int r = tid >> 3;
    int c4 = (tid & 7) << 2;
#pragma unroll
    for (int i = 0; i < 4; i++) {
        int row = r + (i << 5);
        cp16(sbase + (uint32_t)(row * 36 + c4) * 4u, g + (size_t)row * ldg + c4);
    }
}

#define GEMM_TB (128 * 36)
#define GEMM_SMEM (4 * GEMM_TB * 4)

__global__ void __launch_bounds__(256, 2) gemm_nt(const float* __restrict__ A,
                                                  const float* __restrict__ Bm,
                                                  float* __restrict__ C, int K) {
    extern __shared__ float sm[];
    uint32_t sA = (uint32_t)__cvta_generic_to_shared(sm);
    uint32_t sB = sA + 2u * GEMM_TB * 4u;
    int tid = threadIdx.x;
    const float* Ag = A + (size_t)(blockIdx.y * 128) * K;
    const float* Bg = Bm + (size_t)(blockIdx.x * 128) * K;
    int KIT = K >> 5;

    load_tile(Ag, K, sA, tid);
    load_tile(Bg, K, sB, tid);
    asm volatile("cp.async.commit_group;\n" ::: "memory");

    int lane = tid & 31, wid = tid >> 5;
    int g = lane >> 2, tg = lane & 3;
    int wm = (wid & 1) << 6;
    int wn = (wid >> 1) << 5;

    float acc[4][4][4];
#pragma unroll
    for (int a = 0; a < 4; a++)
#pragma unroll
        for (int b = 0; b < 4; b++)
#pragma unroll
            for (int c = 0; c < 4; c++) acc[a][b][c] = 0.f;

    const float* As = sm;
    const float* Bs = sm + 2 * GEMM_TB;

    for (int it = 0; it < KIT; it++) {
        if (it + 1 < KIT) {
            uint32_t nb = ((it + 1) & 1) ? (uint32_t)(GEMM_TB * 4) : 0u;
            load_tile(Ag + (it + 1) * 32, K, sA + nb, tid);
            load_tile(Bg + (it + 1) * 32, K, sB + nb, tid);
            asm volatile("cp.async.commit_group;\n" ::: "memory");
            asm volatile("cp.async.wait_group 1;\n" ::: "memory");
        } else {
            asm volatile("cp.async.wait_group 0;\n" ::: "memory");
        }
        __syncthreads();
        const float* Ac = As + (it & 1) * GEMM_TB;
        const float* Bc = Bs + (it & 1) * GEMM_TB;
#pragma unroll
        for (int ksu = 0; ksu < 4; ksu++) {
            int kc = ksu << 3;
            uint32_t af[4][4], bf[4][2];
#pragma unroll
            for (int mf = 0; mf < 4; mf++) {
                int r0 = wm + (mf << 4) + g;
                af[mf][0] = __float_as_uint(Ac[r0 * 36 + kc + tg]);
                af[mf][1] = __float_as_uint(Ac[(r0 + 8) * 36 + kc + tg]);
                af[mf][2] = __float_as_uint(Ac[r0 * 36 + kc + tg + 4]);
                af[mf][3] = __float_as_uint(Ac[(r0 + 8) * 36 + kc + tg + 4]);
            }
#pragma unroll
            for (int nf = 0; nf < 4; nf++) {
                int n0 = wn + (nf << 3) + g;
                bf[nf][0] = __float_as_uint(Bc[n0 * 36 + kc + tg]);
                bf[nf][1] = __float_as_uint(Bc[n0 * 36 + kc + tg + 4]);
            }
#pragma unroll
            for (int mf = 0; mf < 4; mf++)
#pragma unroll
                for (int nf = 0; nf < 4; nf++)
                    mma_tf32(acc[mf][nf], af[mf], bf[nf]);
        }
        __syncthreads();
    }

    int row0 = (blockIdx.y << 7) + wm + g;
    int col0 = (blockIdx.x << 7) + wn + (tg << 1);
#pragma unroll
    for (int mf = 0; mf < 4; mf++) {
#pragma unroll
        for (int nf = 0; nf < 4; nf++) {
            size_t r = (size_t)(row0 + (mf << 4));
            int c = col0 + (nf << 3);
            float2 v0 = make_float2(acc[mf][nf][0], acc[mf][nf][1]);
            float2 v1 = make_float2(acc[mf][nf][2], acc[mf][nf][3]);
            *reinterpret_cast<float2*>(C + r * 4096 + c) = v0;
            *reinterpret_cast<float2*>(C + (r + 8) * 4096 + c) = v1;
        }
    }
}

// =================================================================================
// Big HMMA tf32 GEMM: Z[8192,4096] = X @ W^T
// R10 config (best): CTA tile 128x128x32, 128 threads (4 warps, warp tile 64x64),
// 3-stage circular cp.async ring, one barrier/iter, 2 CTAs/SM.
// R13 tweaks: (1) de-phase the two co-resident CTAs (odd wave-layer CTAs spin
// ~800 cyc before prologue) so their barrier stalls interleave; (2) issue ksu-0
// LDSMs before the cp.async prefetch burst each iter.
// =================================================================================
#define Z2_TF   (128 * 36)                 // floats per (A or B) stage tile
#define Z2_STG  (2 * Z2_TF)                // 9216 floats = 36864 B per stage
#define Z2_SMEM (3 * Z2_STG * 4)           // 110592 B
#define Z2_KIT  128

__device__ __forceinline__ void z2_load(uint32_t sb, int buf, int it,
                                        const float* Ag, const float* Bg, int tid) {
    int k0 = it << 5;
    uint32_t sA = sb + (uint32_t)buf * (Z2_STG * 4);
    uint32_t sB = sA + Z2_TF * 4;
#pragma unroll
    for (int i = 0; i < 8; i++) {           // A: 1024 float4 over 128 threads
        int idx = tid + (i << 7);
        int r = idx >> 3, c4 = (idx & 7) << 2;
        cp16(sA + (uint32_t)(r * 36 + c4) * 4u, Ag + (size_t)r * IN_F + k0 + c4);
    }
#pragma unroll
    for (int i = 0; i < 8; i++) {           // B: 1024 float4
        int idx = tid + (i << 7);
        int r = idx >> 3, c4 = (idx & 7) << 2;
        cp16(sB + (uint32_t)(r * 36 + c4) * 4u, Bg + (size_t)r * IN_F + k0 + c4);
    }
    asm volatile("cp.async.commit_group;\n" ::: "memory");
}

__global__ void __launch_bounds__(128, 2) zgemm_big(const float* __restrict__ Xg,
                                                    const float* __restrict__ Wg,
                                                    float* __restrict__ Zg) {
    extern __shared__ float sm[];
    uint32_t sb = (uint32_t)__cvta_generic_to_shared(sm);
    int tid = threadIdx.x;
    int lane = tid & 31, wid = tid >> 5;   // 4 warps
    int g = lane >> 2, tg = lane & 3;
    int wm = (wid & 1) << 6;        // 2 warps in m -> 128
    int wn = (wid >> 1) << 6;       // 2 warps in n -> 128 (64 cols each)

    // De-phase: CLC places linear bid and bid+148 on the same SM. Give the odd
    // wave-layer a fixed ~800-cycle dependent-IMAD delay so the two co-resident
    // CTAs' barrier windows interleave instead of coinciding. Deterministic.
    {
        int lin = blockIdx.x + (blockIdx.y << 5);
        if ((lin / 148) & 1) {
            unsigned v = (unsigned)tid + 1u;
#pragma unroll 1
            for (int i = 0; i < 200; i++) v = v * 1664525u + 1013904223u;
            if (v == 0x7FFFFFFFu) sm[0] = (float)v;   // unprovable, never taken
        }
    }

    const float* Ag = Xg + (size_t)blockIdx.y * 128 * IN_F;
    const float* Bg = Wg + (size_t)blockIdx.x * 128 * IN_F;

    // ldmatrix per-lane offsets (bytes, within a stage tile)
    uint32_t aoff = ((uint32_t)(wm + (((lane >> 3) & 1) << 3) + (lane & 7)) * 36u
                     + (uint32_t)((lane >> 4) << 2)) * 4u;
    uint32_t boff = ((uint32_t)(wn + ((lane >> 4) << 3) + (lane & 7)) * 36u
                     + (uint32_t)(((lane >> 3) & 1) << 2)) * 4u;

    // prologue: tiles 0 and 1
    z2_load(sb, 0, 0, Ag, Bg, tid);
    z2_load(sb, 1, 1, Ag, Bg, tid);

    float acc[4][8][4];                    // 64x64 warp tile: 4 m-frags x 8 n-frags
#pragma unroll
    for (int a = 0; a < 4; a++)
#pragma unroll
        for (int b = 0; b < 8; b++)
#pragma unroll
            for (int c = 0; c < 4; c++) acc[a][b][c] = 0.f;

    for (int it = 0; it < Z2_KIT; it++) {
        int b = it % 3;
        if (it == Z2_KIT - 1) asm volatile("cp.async.wait_group 0;\n" ::: "memory");
        else                  asm volatile("cp.async.wait_group 1;\n" ::: "memory");
        __syncthreads();   // all warps done computing iter it-1 -> slot (it+2)%3 free

        uint32_t sAb = sb + (uint32_t)b * (Z2_STG * 4) + aoff;
        uint32_t sBb = sb + (uint32_t)b * (Z2_STG * 4) + Z2_TF * 4 + boff;

        // ksu 0 fragments first (so MMAs can start before/under the cp burst)
        uint32_t af[4][4], bf[4][4];
#pragma unroll
        for (int mf = 0; mf < 4; mf++)
            ldsm4(af[mf][0], af[mf][1], af[mf][2], af[mf][3],
                  sAb + (uint32_t)(mf * 2304));
#pragma unroll
        for (int nfp = 0; nfp < 4; nfp++)
            ldsm4(bf[nfp][0], bf[nfp][1], bf[nfp][2], bf[nfp][3],
                  sBb + (uint32_t)(nfp * 2304));

        if (it + 2 < Z2_KIT) z2_load(sb, (it + 2) % 3, it + 2, Ag, Bg, tid);

#pragma unroll
        for (int mf = 0; mf < 4; mf++)
#pragma unroll
            for (int nf = 0; nf < 8; nf++)
                mma_tf32(acc[mf][nf], af[mf], &bf[nf >> 1][(nf & 1) << 1]);

#pragma unroll
        for (int ksu = 1; ksu < 4; ksu++) {
#pragma unroll
            for (int mf = 0; mf < 4; mf++)
                ldsm4(af[mf][0], af[mf][1], af[mf][2], af[mf][3],
                      sAb + (uint32_t)(mf * 2304 + ksu * 32));   // 16*36*4=2304
#pragma unroll
            for (int nfp = 0; nfp < 4; nfp++)
                ldsm4(bf[nfp][0], bf[nfp][1], bf[nfp][2], bf[nfp][3],
                      sBb + (uint32_t)(nfp * 2304 + ksu * 32));
#pragma unroll
            for (int mf = 0; mf < 4; mf++)
#pragma unroll
                for (int nf = 0; nf < 8; nf++)
                    mma_tf32(acc[mf][nf], af[mf], &bf[nf >> 1][(nf & 1) << 1]);
        }
    }

    int row0 = (blockIdx.y << 7) + wm + g;
    int col0 = (blockIdx.x << 7) + wn + (tg << 1);
#pragma unroll
    for (int mf = 0; mf < 4; mf++) {
#pragma unroll
        for (int nf = 0; nf < 8; nf++) {
            size_t r = (size_t)(row0 + (mf << 4));
            int c = col0 + (nf << 3);
            float2 v0 = make_float2(acc[mf][nf][0], acc[mf][nf][1]);
            float2 v1 = make_float2(acc[mf][nf][2], acc[mf][nf][3]);
            *reinterpret_cast<float2*>(Zg + r * 4096 + c) = v0;
            *reinterpret_cast<float2*>(Zg + (r + 8) * 4096 + c) = v1;
        }
    }
}

// ---------------- launch ----------------
extern "C" void kernel_launch(void* const* d_in, const int* in_sizes, int n_in,
                              void* d_out, int out_size) {
    const float* input   = (const float*)d_in[0];
    const int*   Qidxs   = (const int*)d_in[1];
    const float* cb      = (const float*)d_in[2];
    const float* SU      = (const float*)d_in[3];
    const float* SV      = (const float*)d_in[4];
    const float* A       = (const float*)d_in[5];
    const float* B       = (const float*)d_in[6];
    const float* scaleWH = (const float*)d_in[7];
    const float* bias    = (const float*)d_in[8];
    float* out = (float*)d_out;

    static bool attr_done = false;
    if (!attr_done) {
        bool ok1 = cudaFuncSetAttribute(gemm_nt, cudaFuncAttributeMaxDynamicSharedMemorySize,
                                        GEMM_SMEM) == cudaSuccess;
        bool ok2 = cudaFuncSetAttribute(zgemm_big, cudaFuncAttributeMaxDynamicSharedMemorySize,
                                        Z2_SMEM) == cudaSuccess;
        if (ok1 && ok2) attr_done = true;
    }

    static float *X = nullptr, *W = nullptr, *Z = nullptr, *ABX = nullptr,
                 *XB = nullptr, *AQ = nullptr;
    if (!X) {
        cudaGetSymbolAddress((void**)&X,   g_X);
        cudaGetSymbolAddress((void**)&W,   g_W);
        cudaGetSymbolAddress((void**)&Z,   g_Z);
        cudaGetSymbolAddress((void**)&ABX, g_ABX);
        cudaGetSymbolAddress((void**)&XB,  g_XB);
        cudaGetSymbolAddress((void**)&AQ,  g_AQ);
    }

    c1_kernel<<<16, 256>>>(SU, scaleWH);                                     // 1
    fwht_pre<<<NTOK, 512>>>(input);                                          // 2
    dequant_kernel<<<(OUT_F * (IN_F / 8)) / 256, 256>>>(Qidxs, cb);          // 3
    zgemm_big<<<dim3(32, 64), 128, Z2_SMEM>>>(X, W, Z);                      // 4
    round_a_kernel<<<(OUT_F * RANK) / 256, 256>>>(A);                        // 5
    xb_partial<<<dim3(32, 4), 256>>>(B);                                     // 6
    xb_reduce<<<(NTOK * RANK) / 256, 256>>>();                               // 7
    gemm_nt<<<dim3(32, 64), 256, GEMM_SMEM>>>(XB, AQ, ABX, RANK);            // 8
    fwht_post<<<NTOK, 512>>>(SV, bias, out);                                 // 9
}

// round 14
// speedup vs baseline: 1.1859x; 1.1208x over previous
#include <cuda_runtime.h>
#include <cstdint>

#define IN_F  4096
#define OUT_F 4096
#define NTOK  8192
#define RANK  64

// ---------------- scratch (static device globals; no allocation) ----------------
__device__ float g_X  [(size_t)NTOK * IN_F];    // fwht'd, scaled, tf32-rounded input
__device__ float g_W  [(size_t)OUT_F * IN_F];   // dequantized codebook weights (tf32-rounded)
__device__ float g_Z  [(size_t)NTOK * OUT_F];   // x @ W^T
__device__ float g_ABX[(size_t)NTOK * OUT_F];   // (x B^T) A^T
__device__ float g_XB [NTOK * RANK];            // x @ B^T (tf32-rounded)
__device__ float g_XBp[8 * NTOK * RANK];        // split-K partials for XB (8 splits)
__device__ float g_AQ [OUT_F * RANK];           // tf32-rounded A
__device__ float g_C1 [IN_F];                   // SU / scaleWH

// ---------------- helpers ----------------
__device__ __forceinline__ float tf32r(float f) {
    uint32_t u;
    asm("cvt.rna.tf32.f32 %0, %1;" : "=r"(u) : "f"(f));
    return __uint_as_float(u);
}

#define BFLY(a, b) do { float _u = (a); float _v = (b); (a) = _u + _v; (b) = _u - _v; } while (0)

__device__ __forceinline__ void h8(float e[8]) {
    BFLY(e[0], e[1]); BFLY(e[2], e[3]); BFLY(e[4], e[5]); BFLY(e[6], e[7]);
    BFLY(e[0], e[2]); BFLY(e[1], e[3]); BFLY(e[4], e[6]); BFLY(e[5], e[7]);
    BFLY(e[0], e[4]); BFLY(e[1], e[5]); BFLY(e[2], e[6]); BFLY(e[3], e[7]);
}

// ---------------- tiny prep kernels ----------------
__global__ void c1_kernel(const float* __restrict__ SU, const float* __restrict__ sWH) {
    int i = blockIdx.x * 256 + threadIdx.x;
    if (i < IN_F) g_C1[i] = SU[i] / sWH[i];
}

__global__ void round_a_kernel(const float* __restrict__ A) {
    int i = blockIdx.x * 256 + threadIdx.x;
    if (i < OUT_F * RANK) g_AQ[i] = tf32r(A[i]);
}

// ---------------- dequant: W[m][k] = cb[Q[m][k/8]][k%8], tf32-rounded ----------------
__global__ void dequant_kernel(const int* __restrict__ Q, const float* __restrict__ cb) {
    int i = blockIdx.x * 256 + threadIdx.x;            // 0 .. 4096*512
    if (i >= OUT_F * (IN_F / 8)) return;
    int q = Q[i];
    const float4* c = reinterpret_cast<const float4*>(cb) + ((size_t)q << 1);
    float4 v0 = c[0], v1 = c[1];
    float4 r0, r1;
    r0.x = tf32r(v0.x); r0.y = tf32r(v0.y); r0.z = tf32r(v0.z); r0.w = tf32r(v0.w);
    r1.x = tf32r(v1.x); r1.y = tf32r(v1.y); r1.z = tf32r(v1.z); r1.w = tf32r(v1.w);
    float4* w = reinterpret_cast<float4*>(g_W) + ((size_t)i << 1);
    w[0] = r0; w[1] = r1;
}

// ---------------- FWHT pre: X = fwht(input * C1) / 64, tf32-rounded ----------------
__global__ void __launch_bounds__(512) fwht_pre(const float* __restrict__ in) {
    __shared__ float s[4608];
    int row = blockIdx.x;
    int t = threadIdx.x;
    const float* src = in + (size_t)row * IN_F;
    float e[8];

#pragma unroll
    for (int i = 0; i < 8; i++) { int idx = t + (i << 9); e[i] = src[idx] * g_C1[idx]; }
    h8(e);
#pragma unroll
    for (int i = 0; i < 8; i++) { int idx = t + (i << 9); s[idx + (idx >> 3)] = e[i]; }
    __syncthreads();
    {
        int lo = t & 63, hi = t >> 6;
#pragma unroll
        for (int i = 0; i < 8; i++) { int idx = lo + (i << 6) + (hi << 9); e[i] = s[idx + (idx >> 3)]; }
        h8(e);
#pragma unroll
        for (int i = 0; i < 8; i++) { int idx = lo + (i << 6) + (hi << 9); s[idx + (idx >> 3)] = e[i]; }
    }
    __syncthreads();
    {
        int lo = t & 7, hi = t >> 3;
#pragma unroll
        for (int i = 0; i < 8; i++) { int idx = lo + (i << 3) + (hi << 6); e[i] = s[idx + (idx >> 3)]; }
        h8(e);
#pragma unroll
        for (int i = 0; i < 8; i++) { int idx = lo + (i << 3) + (hi << 6); s[idx + (idx >> 3)] = e[i]; }
    }
    __syncthreads();
    {
#pragma unroll
        for (int i = 0; i < 8; i++) { int idx = (t << 3) + i; e[i] = s[idx + (idx >> 3)]; }
        h8(e);
        float4 o0, o1;
        o0.x = tf32r(e[0] * 0.015625f); o0.y = tf32r(e[1] * 0.015625f);
        o0.z = tf32r(e[2] * 0.015625f); o0.w = tf32r(e[3] * 0.015625f);
        o1.x = tf32r(e[4] * 0.015625f); o1.y = tf32r(e[5] * 0.015625f);
        o1.z = tf32r(e[6] * 0.015625f); o1.w = tf32r(e[7] * 0.015625f);
        float4* dst = reinterpret_cast<float4*>(g_X + (size_t)row * IN_F + (t << 3));
        dst[0] = o0; dst[1] = o1;
    }
}

// ---------------- FWHT post + epilogue ----------------
__global__ void __launch_bounds__(512) fwht_post(const float* __restrict__ SV,
                                                 const float* __restrict__ bias,
                                                 float* __restrict__ out) {
    __shared__ float s[4608];
    int row = blockIdx.x;
    int t = threadIdx.x;
    const float* src = g_Z + (size_t)row * OUT_F;
    float e[8];

#pragma unroll
    for (int i = 0; i < 8; i++) { int idx = t + (i << 9); e[i] = src[idx]; }
    h8(e);
#pragma unroll
    for (int i = 0; i < 8; i++) { int idx = t + (i << 9); s[idx + (idx >> 3)] = e[i]; }
    __syncthreads();
    {
        int lo = t & 63, hi = t >> 6;
#pragma unroll
        for (int i = 0; i < 8; i++) { int idx = lo + (i << 6) + (hi << 9); e[i] = s[idx + (idx >> 3)]; }
        h8(e);
#pragma unroll
        for (int i = 0; i < 8; i++) { int idx = lo + (i << 6) + (hi << 9); s[idx + (idx >> 3)] = e[i]; }
    }
    __syncthreads();
    {
        int lo = t & 7, hi = t >> 3;
#pragma unroll
        for (int i = 0; i < 8; i++) { int idx = lo + (i << 3) + (hi << 6); e[i] = s[idx + (idx >> 3)]; }
        h8(e);
#pragma unroll
        for (int i = 0; i < 8; i++) { int idx = lo + (i << 3) + (hi << 6); s[idx + (idx >> 3)] = e[i]; }
    }
    __syncthreads();
    {
#pragma unroll
        for (int i = 0; i < 8; i++) { int idx = (t << 3) + i; e[i] = s[idx + (idx >> 3)]; }
        h8(e);
        int c0 = t << 3;
        const float4* abx = reinterpret_cast<const float4*>(g_ABX + (size_t)row * OUT_F + c0);
        const float4* sv  = reinterpret_cast<const float4*>(SV + c0);
        const float4* bs  = reinterpret_cast<const float4*>(bias + c0);
        float4 a0 = abx[0], a1 = abx[1];
        float4 s0 = sv[0],  s1 = sv[1];
        float4 b0 = bs[0],  b1 = bs[1];
        float4 o0, o1;
        o0.x = (e[0] * 0.015625f + a0.x) * s0.x + b0.x;
        o0.y = (e[1] * 0.015625f + a0.y) * s0.y + b0.y;
        o0.z = (e[2] * 0.015625f + a0.z) * s0.z + b0.z;
        o0.w = (e[3] * 0.015625f + a0.w) * s0.w + b0.w;
        o1.x = (e[4] * 0.015625f + a1.x) * s1.x + b1.x;
        o1.y = (e[5] * 0.015625f + a1.y) * s1.y + b1.y;
        o1.z = (e[6] * 0.015625f + a1.z) * s1.z + b1.z;
        o1.w = (e[7] * 0.015625f + a1.w) * s1.w + b1.w;
        float4* dst = reinterpret_cast<float4*>(out + (size_t)row * OUT_F + c0);
        dst[0] = o0; dst[1] = o1;
    }
}

// ---------------- shared HMMA helpers ----------------
__device__ __forceinline__ void mma_tf32(float* c, const uint32_t* a, const uint32_t* b) {
    asm volatile(
        "mma.sync.aligned.m16n8k8.row.col.f32.tf32.tf32.f32 "
        "{%0,%1,%2,%3}, {%4,%5,%6,%7}, {%8,%9}, {%0,%1,%2,%3};\n"
        : "+f"(c[0]), "+f"(c[1]), "+f"(c[2]), "+f"(c[3])
        : "r"(a[0]), "r"(a[1]), "r"(a[2]), "r"(a[3]), "r"(b[0]), "r"(b[1]));
}

__device__ __forceinline__ void cp16(uint32_t s, const void* g) {
    asm volatile("cp.async.cg.shared.global [%0], [%1], 16;\n" :: "r"(s), "l"(g) : "memory");
}

__device__ __forceinline__ void ldsm4(uint32_t& r0, uint32_t& r1, uint32_t& r2, uint32_t& r3,
                                      uint32_t addr) {
    asm volatile("ldmatrix.sync.aligned.m8n8.x4.shared.b16 {%0,%1,%2,%3}, [%4];"
                 : "=r"(r0), "=r"(r1), "=r"(r2), "=r"(r3) : "r"(addr));
}

// =================================================================================
// XB = X @ B^T via tf32 MMA split-K: M=8192, N=64, K=4096 split 8 x 512.
// Grid (64 m-blocks, 8 k-splits), 128 threads (4 warps, warp tile 32x64).
// Replaces the FFMA xb_partial (~140us at the 37 TF/s fp32 ceiling) with MMA (~20us).
// =================================================================================
#define XBM_AF   (128 * 36)
#define XBM_BF   (64 * 36)
#define XBM_STG  (XBM_AF + XBM_BF)          // 6912 floats = 27648 B
#define XBM_SMEM (3 * XBM_STG * 4)          // 82944 B
#define XBM_KIT  16

__device__ __forceinline__ void xbm_load(uint32_t sb, int buf, int it,
                                         const float* Ag, const float* Bg, int tid) {
    int k0 = it << 5;
    uint32_t sA = sb + (uint32_t)buf * (XBM_STG * 4);
    uint32_t sB = sA + XBM_AF * 4;
#pragma unroll
    for (int i = 0; i < 8; i++) {            // A: 1024 float4 over 128 threads
        int idx = tid + (i << 7);
        int r = idx >> 3, c4 = (idx & 7) << 2;
        cp16(sA + (uint32_t)(r * 36 + c4) * 4u, Ag + (size_t)r * IN_F + k0 + c4);
    }
#pragma unroll
    for (int i = 0; i < 4; i++) {            // B: 512 float4
        int idx = tid + (i << 7);
        int r = idx >> 3, c4 = (idx & 7) << 2;
        cp16(sB + (uint32_t)(r * 36 + c4) * 4u, Bg + (size_t)r * IN_F + k0 + c4);
    }
    asm volatile("cp.async.commit_group;\n" ::: "memory");
}

__global__ void __launch_bounds__(128, 2) xb_mma(const float* __restrict__ B) {
    extern __shared__ float sm[];
    uint32_t sb = (uint32_t)__cvta_generic_to_shared(sm);
    int tid = threadIdx.x;
    int lane = tid & 31, wid = tid >> 5;
    int g = lane >> 2, tg = lane & 3;
    int wm = wid << 5;                        // warp m offset: 4 warps x 32 rows

    int bm = blockIdx.x;                      // 0..63
    int ks = blockIdx.y;                      // 0..7
    const float* Ag = g_X + (size_t)bm * 128 * IN_F + (ks << 9);
    const float* Bg = B + (ks << 9);

    uint32_t aoff = ((uint32_t)(wm + (((lane >> 3) & 1) << 3) + (lane & 7)) * 36u
                     + (uint32_t)((lane >> 4) << 2)) * 4u;
    uint32_t boff = ((uint32_t)(((lane >> 4) << 3) + (lane & 7)) * 36u
                     + (uint32_t)(((lane >> 3) & 1) << 2)) * 4u;

    xbm_load(sb, 0, 0, Ag, Bg, tid);
    xbm_load(sb, 1, 1, Ag, Bg, tid);

    float acc[2][8][4];
#pragma unroll
    for (int a = 0; a < 2; a++)
#pragma unroll
        for (int b = 0; b < 8; b++)
#pragma unroll
            for (int c = 0; c < 4; c++) acc[a][b][c] = 0.f;

    for (int it = 0; it < XBM_KIT; it++) {
        int b = it % 3;
        if (it == XBM_KIT - 1) asm volatile("cp.async.wait_group 0;\n" ::: "memory");
        else                   asm volatile("cp.async.wait_group 1;\n" ::: "memory");
        __syncthreads();

        if (it + 2 < XBM_KIT) xbm_load(sb, (it + 2) % 3, it + 2, Ag, Bg, tid);

        uint32_t sAb = sb + (uint32_t)b * (XBM_STG * 4) + aoff;
        uint32_t sBb = sb + (uint32_t)b * (XBM_STG * 4) + XBM_AF * 4 + boff;
#pragma unroll
        for (int ksu = 0; ksu < 4; ksu++) {
            uint32_t af[2][4], bf[4][4];
#pragma unroll
            for (int mf = 0; mf < 2; mf++)
                ldsm4(af[mf][0], af[mf][1], af[mf][2], af[mf][3],
                      sAb + (uint32_t)(mf * 2304 + ksu * 32));
#pragma unroll
            for (int nfp = 0; nfp < 4; nfp++)
                ldsm4(bf[nfp][0], bf[nfp][1], bf[nfp][2], bf[nfp][3],
                      sBb + (uint32_t)(nfp * 2304 + ksu * 32));
#pragma unroll
            for (int mf = 0; mf < 2; mf++)
#pragma unroll
                for (int nf = 0; nf < 8; nf++)
                    mma_tf32(acc[mf][nf], af[mf], &bf[nf >> 1][(nf & 1) << 1]);
        }
    }

    // write fp32 partials: rows bm*128 + wm + [mf*16 + g, +8], cols 64
    const size_t S = (size_t)NTOK * RANK;
    int row0 = bm * 128 + wm + g;
    int col0 = tg << 1;
    float* dstb = g_XBp + (size_t)ks * S;
#pragma unroll
    for (int mf = 0; mf < 2; mf++) {
#pragma unroll
        for (int nf = 0; nf < 8; nf++) {
            int r = row0 + (mf << 4);
            int c = col0 + (nf << 3);
            float2 v0 = make_float2(acc[mf][nf][0], acc[mf][nf][1]);
            float2 v1 = make_float2(acc[mf][nf][2], acc[mf][nf][3]);
            *reinterpret_cast<float2*>(dstb + (size_t)r * RANK + c) = v0;
            *reinterpret_cast<float2*>(dstb + (size_t)(r + 8) * RANK + c) = v1;
        }
    }
}

__global__ void xb_reduce() {
    int i = blockIdx.x * 256 + threadIdx.x;   // < 524288
    const size_t S = (size_t)NTOK * RANK;
    float s = 0.f;
#pragma unroll
    for (int k = 0; k < 8; k++) s += g_XBp[(size_t)k * S + i];
    g_XB[i] = tf32r(s);
}

// ---------------- small HMMA tf32 GEMM (ABX, K=64): 128x128 tiles ----------------
__device__ __forceinline__ void load_tile(const float* g, int ldg, uint32_t sbase, int tid) {
    int r = tid >> 3;
    int c4 = (tid & 7) << 2;
#pragma unroll
    for (int i = 0; i < 4; i++) {
        int row = r + (i << 5);
        cp16(sbase + (uint32_t)(row * 36 + c4) * 4u, g + (size_t)row * ldg + c4);
    }
}

#define GEMM_TB (128 * 36)
#define GEMM_SMEM (4 * GEMM_TB * 4)

__global__ void __launch_bounds__(256, 2) gemm_nt(const float* __restrict__ A,
                                                  const float* __restrict__ Bm,
                                                  float* __restrict__ C, int K) {
    extern __shared__ float sm[];
    uint32_t sA = (uint32_t)__cvta_generic_to_shared(sm);
    uint32_t sB = sA + 2u * GEMM_TB * 4u;
    int tid = threadIdx.x;
    const float* Ag = A + (size_t)(blockIdx.y * 128) * K;
    const float* Bg = Bm + (size_t)(blockIdx.x * 128) * K;
    int KIT = K >> 5;

    load_tile(Ag, K, sA, tid);
    load_tile(Bg, K, sB, tid);
    asm volatile("cp.async.commit_group;\n" ::: "memory");

    int lane = tid & 31, wid = tid >> 5;
    int g = lane >> 2, tg = lane & 3;
    int wm = (wid & 1) << 6;
    int wn = (wid >> 1) << 5;

    float acc[4][4][4];
#pragma unroll
    for (int a = 0; a < 4; a++)
#pragma unroll
        for (int b = 0; b < 4; b++)
#pragma unroll
            for (int c = 0; c < 4; c++) acc[a][b][c] = 0.f;

    const float* As = sm;
    const float* Bs = sm + 2 * GEMM_TB;

    for (int it = 0; it < KIT; it++) {
        if (it + 1 < KIT) {
            uint32_t nb = ((it + 1) & 1) ? (uint32_t)(GEMM_TB * 4) : 0u;
            load_tile(Ag + (it + 1) * 32, K, sA + nb, tid);
            load_tile(Bg + (it + 1) * 32, K, sB + nb, tid);
            asm volatile("cp.async.commit_group;\n" ::: "memory");
            asm volatile("cp.async.wait_group 1;\n" ::: "memory");
        } else {
            asm volatile("cp.async.wait_group 0;\n" ::: "memory");
        }
        __syncthreads();
        const float* Ac = As + (it & 1) * GEMM_TB;
        const float* Bc = Bs + (it & 1) * GEMM_TB;
#pragma unroll
        for (int ksu = 0; ksu < 4; ksu++) {
            int kc = ksu << 3;
            uint32_t af[4][4], bf[4][2];
#pragma unroll
            for (int mf = 0; mf < 4; mf++) {
                int r0 = wm + (mf << 4) + g;
                af[mf][0] = __float_as_uint(Ac[r0 * 36 + kc + tg]);
                af[mf][1] = __float_as_uint(Ac[(r0 + 8) * 36 + kc + tg]);
                af[mf][2] = __float_as_uint(Ac[r0 * 36 + kc + tg + 4]);
                af[mf][3] = __float_as_uint(Ac[(r0 + 8) * 36 + kc + tg + 4]);
            }
#pragma unroll
            for (int nf = 0; nf < 4; nf++) {
                int n0 = wn + (nf << 3) + g;
                bf[nf][0] = __float_as_uint(Bc[n0 * 36 + kc + tg]);
                bf[nf][1] = __float_as_uint(Bc[n0 * 36 + kc + tg + 4]);
            }
#pragma unroll
            for (int mf = 0; mf < 4; mf++)
#pragma unroll
                for (int nf = 0; nf < 4; nf++)
                    mma_tf32(acc[mf][nf], af[mf], bf[nf]);
        }
        __syncthreads();
    }

    int row0 = (blockIdx.y << 7) + wm + g;
    int col0 = (blockIdx.x << 7) + wn + (tg << 1);
#pragma unroll
    for (int mf = 0; mf < 4; mf++) {
#pragma unroll
        for (int nf = 0; nf < 4; nf++) {
            size_t r = (size_t)(row0 + (mf << 4));
            int c = col0 + (nf << 3);
            float2 v0 = make_float2(acc[mf][nf][0], acc[mf][nf][1]);
            float2 v1 = make_float2(acc[mf][nf][2], acc[mf][nf][3]);
            *reinterpret_cast<float2*>(C + r * 4096 + c) = v0;
            *reinterpret_cast<float2*>(C + (r + 8) * 4096 + c) = v1;
        }
    }
}

// =================================================================================
// Big HMMA tf32 GEMM: Z[8192,4096] = X @ W^T  — exact R10 best config.
// CTA tile 128x128x32, 128 threads (4 warps, warp tile 64x64), 3-stage circular
// cp.async ring, one __syncthreads/iter, 2 CTAs/SM, LDSM fragments.
// =================================================================================
#define Z2_TF   (128 * 36)                 // floats per (A or B) stage tile
#define Z2_STG  (2 * Z2_TF)                // 9216 floats = 36864 B per stage
#define Z2_SMEM (3 * Z2_STG * 4)           // 110592 B
#define Z2_KIT  128

__device__ __forceinline__ void z2_load(uint32_t sb, int buf, int it,
                                        const float* Ag, const float* Bg, int tid) {
    int k0 = it << 5;
    uint32_t sA = sb + (uint32_t)buf * (Z2_STG * 4);
    uint32_t sB = sA + Z2_TF * 4;
#pragma unroll
    for (int i = 0; i < 8; i++) {           // A: 1024 float4 over 128 threads
        int idx = tid + (i << 7);
        int r = idx >> 3, c4 = (idx & 7) << 2;
        cp16(sA + (uint32_t)(r * 36 + c4) * 4u, Ag + (size_t)r * IN_F + k0 + c4);
    }
#pragma unroll
    for (int i = 0; i < 8; i++) {           // B: 1024 float4
        int idx = tid + (i << 7);
        int r = idx >> 3, c4 = (idx & 7) << 2;
        cp16(sB + (uint32_t)(r * 36 + c4) * 4u, Bg + (size_t)r * IN_F + k0 + c4);
    }
    asm volatile("cp.async.commit_group;\n" ::: "memory");
}

__global__ void __launch_bounds__(128, 2) zgemm_big(const float* __restrict__ Xg,
                                                    const float* __restrict__ Wg,
                                                    float* __restrict__ Zg) {
    extern __shared__ float sm[];
    uint32_t sb = (uint32_t)__cvta_generic_to_shared(sm);
    int tid = threadIdx.x;
    int lane = tid & 31, wid = tid >> 5;   // 4 warps
    int g = lane >> 2, tg = lane & 3;
    int wm = (wid & 1) << 6;        // 2 warps in m -> 128
    int wn = (wid >> 1) << 6;       // 2 warps in n -> 128 (64 cols each)

    const float* Ag = Xg + (size_t)blockIdx.y * 128 * IN_F;
    const float* Bg = Wg + (size_t)blockIdx.x * 128 * IN_F;

    // ldmatrix per-lane offsets (bytes, within a stage tile)
    uint32_t aoff = ((uint32_t)(wm + (((lane >> 3) & 1) << 3) + (lane & 7)) * 36u
                     + (uint32_t)((lane >> 4) << 2)) * 4u;
    uint32_t boff = ((uint32_t)(wn + ((lane >> 4) << 3) + (lane & 7)) * 36u
                     + (uint32_t)(((lane >> 3) & 1) << 2)) * 4u;

    // prologue: tiles 0 and 1
    z2_load(sb, 0, 0, Ag, Bg, tid);
    z2_load(sb, 1, 1, Ag, Bg, tid);

    float acc[4][8][4];                    // 64x64 warp tile: 4 m-frags x 8 n-frags
#pragma unroll
    for (int a = 0; a < 4; a++)
#pragma unroll
        for (int b = 0; b < 8; b++)
#pragma unroll
            for (int c = 0; c < 4; c++) acc[a][b][c] = 0.f;

    for (int it = 0; it < Z2_KIT; it++) {
        int b = it % 3;
        if (it == Z2_KIT - 1) asm volatile("cp.async.wait_group 0;\n" ::: "memory");
        else                  asm volatile("cp.async.wait_group 1;\n" ::: "memory");
        __syncthreads();   // all warps done computing iter it-1 -> slot (it+2)%3 free

        if (it + 2 < Z2_KIT) z2_load(sb, (it + 2) % 3, it + 2, Ag, Bg, tid);

        uint32_t sAb = sb + (uint32_t)b * (Z2_STG * 4) + aoff;
        uint32_t sBb = sb + (uint32_t)b * (Z2_STG * 4) + Z2_TF * 4 + boff;
#pragma unroll
        for (int ksu = 0; ksu < 4; ksu++) {
            uint32_t af[4][4], bf[4][4];
#pragma unroll
            for (int mf = 0; mf < 4; mf++)
                ldsm4(af[mf][0], af[mf][1], af[mf][2], af[mf][3],
                      sAb + (uint32_t)(mf * 2304 + ksu * 32));   // 16*36*4=2304
#pragma unroll
            for (int nfp = 0; nfp < 4; nfp++)
                ldsm4(bf[nfp][0], bf[nfp][1], bf[nfp][2], bf[nfp][3],
                      sBb + (uint32_t)(nfp * 2304 + ksu * 32));
#pragma unroll
            for (int mf = 0; mf < 4; mf++)
#pragma unroll
                for (int nf = 0; nf < 8; nf++)
                    mma_tf32(acc[mf][nf], af[mf], &bf[nf >> 1][(nf & 1) << 1]);
        }
    }

    int row0 = (blockIdx.y << 7) + wm + g;
    int col0 = (blockIdx.x << 7) + wn + (tg << 1);
#pragma unroll
    for (int mf = 0; mf < 4; mf++) {
#pragma unroll
        for (int nf = 0; nf < 8; nf++) {
            size_t r = (size_t)(row0 + (mf << 4));
            int c = col0 + (nf << 3);
            float2 v0 = make_float2(acc[mf][nf][0], acc[mf][nf][1]);
            float2 v1 = make_float2(acc[mf][nf][2], acc[mf][nf][3]);
            *reinterpret_cast<float2*>(Zg + r * 4096 + c) = v0;
            *reinterpret_cast<float2*>(Zg + (r + 8) * 4096 + c) = v1;
        }
    }
}

// ---------------- launch ----------------
extern "C" void kernel_launch(void* const* d_in, const int* in_sizes, int n_in,
                              void* d_out, int out_size) {
    const float* input   = (const float*)d_in[0];
    const int*   Qidxs   = (const int*)d_in[1];
    const float* cb      = (const float*)d_in[2];
    const float* SU      = (const float*)d_in[3];
    const float* SV      = (const float*)d_in[4];
    const float* A       = (const float*)d_in[5];
    const float* B       = (const float*)d_in[6];
    const float* scaleWH = (const float*)d_in[7];
    const float* bias    = (const float*)d_in[8];
    float* out = (float*)d_out;

    static bool attr_done = false;
    if (!attr_done) {
        bool ok1 = cudaFuncSetAttribute(gemm_nt, cudaFuncAttributeMaxDynamicSharedMemorySize,
                                        GEMM_SMEM) == cudaSuccess;
        bool ok2 = cudaFuncSetAttribute(zgemm_big, cudaFuncAttributeMaxDynamicSharedMemorySize,
                                        Z2_SMEM) == cudaSuccess;
        bool ok3 = cudaFuncSetAttribute(xb_mma, cudaFuncAttributeMaxDynamicSharedMemorySize,
                                        XBM_SMEM) == cudaSuccess;
        if (ok1 && ok2 && ok3) attr_done = true;
    }

    static float *X = nullptr, *W = nullptr, *Z = nullptr, *ABX = nullptr,
                 *XB = nullptr, *AQ = nullptr;
    if (!X) {
        cudaGetSymbolAddress((void**)&X,   g_X);
        cudaGetSymbolAddress((void**)&W,   g_W);
        cudaGetSymbolAddress((void**)&Z,   g_Z);
        cudaGetSymbolAddress((void**)&ABX, g_ABX);
        cudaGetSymbolAddress((void**)&XB,  g_XB);
        cudaGetSymbolAddress((void**)&AQ,  g_AQ);
    }

    c1_kernel<<<16, 256>>>(SU, scaleWH);                                     // 1
    fwht_pre<<<NTOK, 512>>>(input);                                          // 2
    dequant_kernel<<<(OUT_F * (IN_F / 8)) / 256, 256>>>(Qidxs, cb);          // 3
    zgemm_big<<<dim3(32, 64), 128, Z2_SMEM>>>(X, W, Z);                      // 4
    round_a_kernel<<<(OUT_F * RANK) / 256, 256>>>(A);                        // 5
    xb_mma<<<dim3(64, 8), 128, XBM_SMEM>>>(B);                               // 6
    xb_reduce<<<(NTOK * RANK) / 256, 256>>>();                               // 7
    gemm_nt<<<dim3(32, 64), 256, GEMM_SMEM>>>(XB, AQ, ABX, RANK);            // 8
    fwht_post<<<NTOK, 512>>>(SV, bias, out);                                 // 9
}

// round 15
// speedup vs baseline: 1.2219x; 1.0304x over previous
#include <cuda_runtime.h>
#include <cstdint>

#define IN_F  4096
#define OUT_F 4096
#define NTOK  8192
#define RANK  64

// ---------------- scratch (static device globals; no allocation) ----------------
__device__ float g_X  [(size_t)NTOK * IN_F];    // fwht'd, scaled, tf32-rounded input
__device__ float g_W  [(size_t)OUT_F * IN_F];   // dequantized codebook weights (tf32-rounded)
__device__ float g_Z  [(size_t)NTOK * OUT_F];   // x @ W^T
__device__ float g_ABX[(size_t)NTOK * OUT_F];   // (x B^T) A^T
__device__ float g_XB [NTOK * RANK];            // x @ B^T (tf32-rounded)
__device__ float g_XBp[8 * NTOK * RANK];        // split-K partials for XB (8 splits)
__device__ float g_AQ [OUT_F * RANK];           // tf32-rounded A
__device__ float g_C1 [IN_F];                   // SU / scaleWH

// ---------------- helpers ----------------
__device__ __forceinline__ float tf32r(float f) {
    uint32_t u;
    asm("cvt.rna.tf32.f32 %0, %1;" : "=r"(u) : "f"(f));
    return __uint_as_float(u);
}

#define BFLY(a, b) do { float _u = (a); float _v = (b); (a) = _u + _v; (b) = _u - _v; } while (0)

__device__ __forceinline__ void h8(float e[8]) {
    BFLY(e[0], e[1]); BFLY(e[2], e[3]); BFLY(e[4], e[5]); BFLY(e[6], e[7]);
    BFLY(e[0], e[2]); BFLY(e[1], e[3]); BFLY(e[4], e[6]); BFLY(e[5], e[7]);
    BFLY(e[0], e[4]); BFLY(e[1], e[5]); BFLY(e[2], e[6]); BFLY(e[3], e[7]);
}

// ---------------- tiny prep kernels ----------------
__global__ void c1_kernel(const float* __restrict__ SU, const float* __restrict__ sWH) {
    int i = blockIdx.x * 256 + threadIdx.x;
    if (i < IN_F) g_C1[i] = SU[i] / sWH[i];
}

__global__ void round_a_kernel(const float* __restrict__ A) {
    int i = blockIdx.x * 256 + threadIdx.x;
    if (i < OUT_F * RANK) g_AQ[i] = tf32r(A[i]);
}

// ---------------- dequant: W[m][k] = cb[Q[m][k/8]][k%8], tf32-rounded ----------------
__global__ void dequant_kernel(const int* __restrict__ Q, const float* __restrict__ cb) {
    int i = blockIdx.x * 256 + threadIdx.x;            // 0 .. 4096*512
    if (i >= OUT_F * (IN_F / 8)) return;
    int q = Q[i];
    const float4* c = reinterpret_cast<const float4*>(cb) + ((size_t)q << 1);
    float4 v0 = c[0], v1 = c[1];
    float4 r0, r1;
    r0.x = tf32r(v0.x); r0.y = tf32r(v0.y); r0.z = tf32r(v0.z); r0.w = tf32r(v0.w);
    r1.x = tf32r(v1.x); r1.y = tf32r(v1.y); r1.z = tf32r(v1.z); r1.w = tf32r(v1.w);
    float4* w = reinterpret_cast<float4*>(g_W) + ((size_t)i << 1);
    w[0] = r0; w[1] = r1;
}

// ---------------- FWHT pre: X = fwht(input * C1) / 64, tf32-rounded ----------------
__global__ void __launch_bounds__(512) fwht_pre(const float* __restrict__ in) {
    __shared__ float s[4608];
    int row = blockIdx.x;
    int t = threadIdx.x;
    const float* src = in + (size_t)row * IN_F;
    float e[8];

#pragma unroll
    for (int i = 0; i < 8; i++) { int idx = t + (i << 9); e[i] = src[idx] * g_C1[idx]; }
    h8(e);
#pragma unroll
    for (int i = 0; i < 8; i++) { int idx = t + (i << 9); s[idx + (idx >> 3)] = e[i]; }
    __syncthreads();
    {
        int lo = t & 63, hi = t >> 6;
#pragma unroll
        for (int i = 0; i < 8; i++) { int idx = lo + (i << 6) + (hi << 9); e[i] = s[idx + (idx >> 3)]; }
        h8(e);
#pragma unroll
        for (int i = 0; i < 8; i++) { int idx = lo + (i << 6) + (hi << 9); s[idx + (idx >> 3)] = e[i]; }
    }
    __syncthreads();
    {
        int lo = t & 7, hi = t >> 3;
#pragma unroll
        for (int i = 0; i < 8; i++) { int idx = lo + (i << 3) + (hi << 6); e[i] = s[idx + (idx >> 3)]; }
        h8(e);
#pragma unroll
        for (int i = 0; i < 8; i++) { int idx = lo + (i << 3) + (hi << 6); s[idx + (idx >> 3)] = e[i]; }
    }
    __syncthreads();
    {
#pragma unroll
        for (int i = 0; i < 8; i++) { int idx = (t << 3) + i; e[i] = s[idx + (idx >> 3)]; }
        h8(e);
        float4 o0, o1;
        o0.x = tf32r(e[0] * 0.015625f); o0.y = tf32r(e[1] * 0.015625f);
        o0.z = tf32r(e[2] * 0.015625f); o0.w = tf32r(e[3] * 0.015625f);
        o1.x = tf32r(e[4] * 0.015625f); o1.y = tf32r(e[5] * 0.015625f);
        o1.z = tf32r(e[6] * 0.015625f); o1.w = tf32r(e[7] * 0.015625f);
        float4* dst = reinterpret_cast<float4*>(g_X + (size_t)row * IN_F + (t << 3));
        dst[0] = o0; dst[1] = o1;
    }
}

// ---------------- FWHT post + epilogue ----------------
__global__ void __launch_bounds__(512) fwht_post(const float* __restrict__ SV,
                                                 const float* __restrict__ bias,
                                                 float* __restrict__ out) {
    __shared__ float s[4608];
    int row = blockIdx.x;
    int t = threadIdx.x;
    const float* src = g_Z + (size_t)row * OUT_F;
    float e[8];

#pragma unroll
    for (int i = 0; i < 8; i++) { int idx = t + (i << 9); e[i] = src[idx]; }
    h8(e);
#pragma unroll
    for (int i = 0; i < 8; i++) { int idx = t + (i << 9); s[idx + (idx >> 3)] = e[i]; }
    __syncthreads();
    {
        int lo = t & 63, hi = t >> 6;
#pragma unroll
        for (int i = 0; i < 8; i++) { int idx = lo + (i << 6) + (hi << 9); e[i] = s[idx + (idx >> 3)]; }
        h8(e);
#pragma unroll
        for (int i = 0; i < 8; i++) { int idx = lo + (i << 6) + (hi << 9); s[idx + (idx >> 3)] = e[i]; }
    }
    __syncthreads();
    {
        int lo = t & 7, hi = t >> 3;
#pragma unroll
        for (int i = 0; i < 8; i++) { int idx = lo + (i << 3) + (hi << 6); e[i] = s[idx + (idx >> 3)]; }
        h8(e);
#pragma unroll
        for (int i = 0; i < 8; i++) { int idx = lo + (i << 3) + (hi << 6); s[idx + (idx >> 3)] = e[i]; }
    }
    __syncthreads();
    {
#pragma unroll
        for (int i = 0; i < 8; i++) { int idx = (t << 3) + i; e[i] = s[idx + (idx >> 3)]; }
        h8(e);
        int c0 = t << 3;
        const float4* abx = reinterpret_cast<const float4*>(g_ABX + (size_t)row * OUT_F + c0);
        const float4* sv  = reinterpret_cast<const float4*>(SV + c0);
        const float4* bs  = reinterpret_cast<const float4*>(bias + c0);
        float4 a0 = abx[0], a1 = abx[1];
        float4 s0 = sv[0],  s1 = sv[1];
        float4 b0 = bs[0],  b1 = bs[1];
        float4 o0, o1;
        o0.x = (e[0] * 0.015625f + a0.x) * s0.x + b0.x;
        o0.y = (e[1] * 0.015625f + a0.y) * s0.y + b0.y;
        o0.z = (e[2] * 0.015625f + a0.z) * s0.z + b0.z;
        o0.w = (e[3] * 0.015625f + a0.w) * s0.w + b0.w;
        o1.x = (e[4] * 0.015625f + a1.x) * s1.x + b1.x;
        o1.y = (e[5] * 0.015625f + a1.y) * s1.y + b1.y;
        o1.z = (e[6] * 0.015625f + a1.z) * s1.z + b1.z;
        o1.w = (e[7] * 0.015625f + a1.w) * s1.w + b1.w;
        float4* dst = reinterpret_cast<float4*>(out + (size_t)row * OUT_F + c0);
        dst[0] = o0; dst[1] = o1;
    }
}

// ---------------- shared HMMA helpers ----------------
__device__ __forceinline__ void mma_tf32(float* c, const uint32_t* a, const uint32_t* b) {
    asm volatile(
        "mma.sync.aligned.m16n8k8.row.col.f32.tf32.tf32.f32 "
        "{%0,%1,%2,%3}, {%4,%5,%6,%7}, {%8,%9}, {%0,%1,%2,%3};\n"
        : "+f"(c[0]), "+f"(c[1]), "+f"(c[2]), "+f"(c[3])
        : "r"(a[0]), "r"(a[1]), "r"(a[2]), "r"(a[3]), "r"(b[0]), "r"(b[1]));
}

__device__ __forceinline__ void cp16(uint32_t s, const void* g) {
    asm volatile("cp.async.cg.shared.global [%0], [%1], 16;\n" :: "r"(s), "l"(g) : "memory");
}

__device__ __forceinline__ void ldsm4(uint32_t& r0, uint32_t& r1, uint32_t& r2, uint32_t& r3,
                                      uint32_t addr) {
    asm volatile("ldmatrix.sync.aligned.m8n8.x4.shared.b16 {%0,%1,%2,%3}, [%4];"
                 : "=r"(r0), "=r"(r1), "=r"(r2), "=r"(r3) : "r"(addr));
}

// =================================================================================
// XB = X @ B^T via tf32 MMA split-K: M=8192, N=64, K=4096 split 8 x 512.
// =================================================================================
#define XBM_AF   (128 * 36)
#define XBM_BF   (64 * 36)
#define XBM_STG  (XBM_AF + XBM_BF)          // 6912 floats = 27648 B
#define XBM_SMEM (3 * XBM_STG * 4)          // 82944 B
#define XBM_KIT  16

__device__ __forceinline__ void xbm_load(uint32_t sb, int buf, int it,
                                         const float* Ag, const float* Bg, int tid) {
    int k0 = it << 5;
    uint32_t sA = sb + (uint32_t)buf * (XBM_STG * 4);
    uint32_t sB = sA + XBM_AF * 4;
#pragma unroll
    for (int i = 0; i < 8; i++) {            // A: 1024 float4 over 128 threads
        int idx = tid + (i << 7);
        int r = idx >> 3, c4 = (idx & 7) << 2;
        cp16(sA + (uint32_t)(r * 36 + c4) * 4u, Ag + (size_t)r * IN_F + k0 + c4);
    }
#pragma unroll
    for (int i = 0; i < 4; i++) {            // B: 512 float4
        int idx = tid + (i << 7);
        int r = idx >> 3, c4 = (idx & 7) << 2;
        cp16(sB + (uint32_t)(r * 36 + c4) * 4u, Bg + (size_t)r * IN_F + k0 + c4);
    }
    asm volatile("cp.async.commit_group;\n" ::: "memory");
}

__global__ void __launch_bounds__(128, 2) xb_mma(const float* __restrict__ B) {
    extern __shared__ float sm[];
    uint32_t sb = (uint32_t)__cvta_generic_to_shared(sm);
    int tid = threadIdx.x;
    int lane = tid & 31, wid = tid >> 5;
    int g = lane >> 2, tg = lane & 3;
    int wm = wid << 5;                        // warp m offset: 4 warps x 32 rows

    int bm = blockIdx.x;                      // 0..63
    int ks = blockIdx.y;                      // 0..7
    const float* Ag = g_X + (size_t)bm * 128 * IN_F + (ks << 9);
    const float* Bg = B + (ks << 9);

    uint32_t aoff = ((uint32_t)(wm + (((lane >> 3) & 1) << 3) + (lane & 7)) * 36u
                     + (uint32_t)((lane >> 4) << 2)) * 4u;
    uint32_t boff = ((uint32_t)(((lane >> 4) << 3) + (lane & 7)) * 36u
                     + (uint32_t)(((lane >> 3) & 1) << 2)) * 4u;

    xbm_load(sb, 0, 0, Ag, Bg, tid);
    xbm_load(sb, 1, 1, Ag, Bg, tid);

    float acc[2][8][4];
#pragma unroll
    for (int a = 0; a < 2; a++)
#pragma unroll
        for (int b = 0; b < 8; b++)
#pragma unroll
            for (int c = 0; c < 4; c++) acc[a][b][c] = 0.f;

    for (int it = 0; it < XBM_KIT; it++) {
        int b = it % 3;
        if (it == XBM_KIT - 1) asm volatile("cp.async.wait_group 0;\n" ::: "memory");
        else                   asm volatile("cp.async.wait_group 1;\n" ::: "memory");
        __syncthreads();

        if (it + 2 < XBM_KIT) xbm_load(sb, (it + 2) % 3, it + 2, Ag, Bg, tid);

        uint32_t sAb = sb + (uint32_t)b * (XBM_STG * 4) + aoff;
        uint32_t sBb = sb + (uint32_t)b * (XBM_STG * 4) + XBM_AF * 4 + boff;
#pragma unroll
        for (int ksu = 0; ksu < 4; ksu++) {
            uint32_t af[2][4], bf[4][4];
#pragma unroll
            for (int mf = 0; mf < 2; mf++)
                ldsm4(af[mf][0], af[mf][1], af[mf][2], af[mf][3],
                      sAb + (uint32_t)(mf * 2304 + ksu * 32));
#pragma unroll
            for (int nfp = 0; nfp < 4; nfp++)
                ldsm4(bf[nfp][0], bf[nfp][1], bf[nfp][2], bf[nfp][3],
                      sBb + (uint32_t)(nfp * 2304 + ksu * 32));
#pragma unroll
            for (int mf = 0; mf < 2; mf++)
#pragma unroll
                for (int nf = 0; nf < 8; nf++)
                    mma_tf32(acc[mf][nf], af[mf], &bf[nf >> 1][(nf & 1) << 1]);
        }
    }

    const size_t S = (size_t)NTOK * RANK;
    int row0 = bm * 128 + wm + g;
    int col0 = tg << 1;
    float* dstb = g_XBp + (size_t)ks * S;
#pragma unroll
    for (int mf = 0; mf < 2; mf++) {
#pragma unroll
        for (int nf = 0; nf < 8; nf++) {
            int r = row0 + (mf << 4);
            int c = col0 + (nf << 3);
            float2 v0 = make_float2(acc[mf][nf][0], acc[mf][nf][1]);
            float2 v1 = make_float2(acc[mf][nf][2], acc[mf][nf][3]);
            *reinterpret_cast<float2*>(dstb + (size_t)r * RANK + c) = v0;
            *reinterpret_cast<float2*>(dstb + (size_t)(r + 8) * RANK + c) = v1;
        }
    }
}

__global__ void xb_reduce() {
    int i = blockIdx.x * 256 + threadIdx.x;   // < 524288
    const size_t S = (size_t)NTOK * RANK;
    float s = 0.f;
#pragma unroll
    for (int k = 0; k < 8; k++) s += g_XBp[(size_t)k * S + i];
    g_XB[i] = tf32r(s);
}

// ---------------- small HMMA tf32 GEMM (ABX, K=64): 128x128 tiles ----------------
__device__ __forceinline__ void load_tile(const float* g, int ldg, uint32_t sbase, int tid) {
    int r = tid >> 3;
    int c4 = (tid & 7) << 2;
#pragma unroll
    for (int i = 0; i < 4; i++) {
        int row = r + (i << 5);
        cp16(sbase + (uint32_t)(row * 36 + c4) * 4u, g + (size_t)row * ldg + c4);
    }
}

#define GEMM_TB (128 * 36)
#define GEMM_SMEM (4 * GEMM_TB * 4)

__global__ void __launch_bounds__(256, 2) gemm_nt(const float* __restrict__ A,
                                                  const float* __restrict__ Bm,
                                                  float* __restrict__ C, int K) {
    extern __shared__ float sm[];
    uint32_t sA = (uint32_t)__cvta_generic_to_shared(sm);
    uint32_t sB = sA + 2u * GEMM_TB * 4u;
    int tid = threadIdx.x;
    const float* Ag = A + (size_t)(blockIdx.y * 128) * K;
    const float* Bg = Bm + (size_t)(blockIdx.x * 128) * K;
    int KIT = K >> 5;

    load_tile(Ag, K, sA, tid);
    load_tile(Bg, K, sB, tid);
    asm volatile("cp.async.commit_group;\n" ::: "memory");

    int lane = tid & 31, wid = tid >> 5;
    int g = lane >> 2, tg = lane & 3;
    int wm = (wid & 1) << 6;
    int wn = (wid >> 1) << 5;

    float acc[4][4][4];
#pragma unroll
    for (int a = 0; a < 4; a++)
#pragma unroll
        for (int b = 0; b < 4; b++)
#pragma unroll
            for (int c = 0; c < 4; c++) acc[a][b][c] = 0.f;

    const float* As = sm;
    const float* Bs = sm + 2 * GEMM_TB;

    for (int it = 0; it < KIT; it++) {
        if (it + 1 < KIT) {
            uint32_t nb = ((it + 1) & 1) ? (uint32_t)(GEMM_TB * 4) : 0u;
            load_tile(Ag + (it + 1) * 32, K, sA + nb, tid);
            load_tile(Bg + (it + 1) * 32, K, sB + nb, tid);
            asm volatile("cp.async.commit_group;\n" ::: "memory");
            asm volatile("cp.async.wait_group 1;\n" ::: "memory");
        } else {
            asm volatile("cp.async.wait_group 0;\n" ::: "memory");
        }
        __syncthreads();
        const float* Ac = As + (it & 1) * GEMM_TB;
        const float* Bc = Bs + (it & 1) * GEMM_TB;
#pragma unroll
        for (int ksu = 0; ksu < 4; ksu++) {
            int kc = ksu << 3;
            uint32_t af[4][4], bf[4][2];
#pragma unroll
            for (int mf = 0; mf < 4; mf++) {
                int r0 = wm + (mf << 4) + g;
                af[mf][0] = __float_as_uint(Ac[r0 * 36 + kc + tg]);
                af[mf][1] = __float_as_uint(Ac[(r0 + 8) * 36 + kc + tg]);
                af[mf][2] = __float_as_uint(Ac[r0 * 36 + kc + tg + 4]);
                af[mf][3] = __float_as_uint(Ac[(r0 + 8) * 36 + kc + tg + 4]);
            }
#pragma unroll
            for (int nf = 0; nf < 4; nf++) {
                int n0 = wn + (nf << 3) + g;
                bf[nf][0] = __float_as_uint(Bc[n0 * 36 + kc + tg]);
                bf[nf][1] = __float_as_uint(Bc[n0 * 36 + kc + tg + 4]);
            }
#pragma unroll
            for (int mf = 0; mf < 4; mf++)
#pragma unroll
                for (int nf = 0; nf < 4; nf++)
                    mma_tf32(acc[mf][nf], af[mf], bf[nf]);
        }
        __syncthreads();
    }

    int row0 = (blockIdx.y << 7) + wm + g;
    int col0 = (blockIdx.x << 7) + wn + (tg << 1);
#pragma unroll
    for (int mf = 0; mf < 4; mf++) {
#pragma unroll
        for (int nf = 0; nf < 4; nf++) {
            size_t r = (size_t)(row0 + (mf << 4));
            int c = col0 + (nf << 3);
            float2 v0 = make_float2(acc[mf][nf][0], acc[mf][nf][1]);
            float2 v1 = make_float2(acc[mf][nf][2], acc[mf][nf][3]);
            *reinterpret_cast<float2*>(C + r * 4096 + c) = v0;
            *reinterpret_cast<float2*>(C + (r + 8) * 4096 + c) = v1;
        }
    }
}

// =================================================================================
// Big HMMA tf32 GEMM: Z[8192,4096] = X @ W^T  — exact R10 best config.
// =================================================================================
#define Z2_TF   (128 * 36)                 // floats per (A or B) stage tile
#define Z2_STG  (2 * Z2_TF)                // 9216 floats = 36864 B per stage
#define Z2_SMEM (3 * Z2_STG * 4)           // 110592 B
#define Z2_KIT  128

__device__ __forceinline__ void z2_load(uint32_t sb, int buf, int it,
                                        const float* Ag, const float* Bg, int tid) {
    int k0 = it << 5;
    uint32_t sA = sb + (uint32_t)buf * (Z2_STG * 4);
    uint32_t sB = sA + Z2_TF * 4;
#pragma unroll
    for (int i = 0; i < 8; i++) {           // A: 1024 float4 over 128 threads
        int idx = tid + (i << 7);
        int r = idx >> 3, c4 = (idx & 7) << 2;
        cp16(sA + (uint32_t)(r * 36 + c4) * 4u, Ag + (size_t)r * IN_F + k0 + c4);
    }
#pragma unroll
    for (int i = 0; i < 8; i++) {           // B: 1024 float4
        int idx = tid + (i << 7);
        int r = idx >> 3, c4 = (idx & 7) << 2;
        cp16(sB + (uint32_t)(r * 36 + c4) * 4u, Bg + (size_t)r * IN_F + k0 + c4);
    }
    asm volatile("cp.async.commit_group;\n" ::: "memory");
}

__global__ void __launch_bounds__(128, 2) zgemm_big(const float* __restrict__ Xg,
                                                    const float* __restrict__ Wg,
                                                    float* __restrict__ Zg) {
    extern __shared__ float sm[];
    uint32_t sb = (uint32_t)__cvta_generic_to_shared(sm);
    int tid = threadIdx.x;
    int lane = tid & 31, wid = tid >> 5;   // 4 warps
    int g = lane >> 2, tg = lane & 3;
    int wm = (wid & 1) << 6;        // 2 warps in m -> 128
    int wn = (wid >> 1) << 6;       // 2 warps in n -> 128 (64 cols each)

    const float* Ag = Xg + (size_t)blockIdx.y * 128 * IN_F;
    const float* Bg = Wg + (size_t)blockIdx.x * 128 * IN_F;

    uint32_t aoff = ((uint32_t)(wm + (((lane >> 3) & 1) << 3) + (lane & 7)) * 36u
                     + (uint32_t)((lane >> 4) << 2)) * 4u;
    uint32_t boff = ((uint32_t)(wn + ((lane >> 4) << 3) + (lane & 7)) * 36u
                     + (uint32_t)(((lane >> 3) & 1) << 2)) * 4u;

    z2_load(sb, 0, 0, Ag, Bg, tid);
    z2_load(sb, 1, 1, Ag, Bg, tid);

    float acc[4][8][4];                    // 64x64 warp tile: 4 m-frags x 8 n-frags
#pragma unroll
    for (int a = 0; a < 4; a++)
#pragma unroll
        for (int b = 0; b < 8; b++)
#pragma unroll
            for (int c = 0; c < 4; c++) acc[a][b][c] = 0.f;

    for (int it = 0; it < Z2_KIT; it++) {
        int b = it % 3;
        if (it == Z2_KIT - 1) asm volatile("cp.async.wait_group 0;\n" ::: "memory");
        else                  asm volatile("cp.async.wait_group 1;\n" ::: "memory");
        __syncthreads();   // all warps done computing iter it-1 -> slot (it+2)%3 free

        if (it + 2 < Z2_KIT) z2_load(sb, (it + 2) % 3, it + 2, Ag, Bg, tid);

        uint32_t sAb = sb + (uint32_t)b * (Z2_STG * 4) + aoff;
        uint32_t sBb = sb + (uint32_t)b * (Z2_STG * 4) + Z2_TF * 4 + boff;
#pragma unroll
        for (int ksu = 0; ksu < 4; ksu++) {
            uint32_t af[4][4], bf[4][4];
#pragma unroll
            for (int mf = 0; mf < 4; mf++)
                ldsm4(af[mf][0], af[mf][1], af[mf][2], af[mf][3],
                      sAb + (uint32_t)(mf * 2304 + ksu * 32));   // 16*36*4=2304
#pragma unroll
            for (int nfp = 0; nfp < 4; nfp++)
                ldsm4(bf[nfp][0], bf[nfp][1], bf[nfp][2], bf[nfp][3],
                      sBb + (uint32_t)(nfp * 2304 + ksu * 32));
#pragma unroll
            for (int mf = 0; mf < 4; mf++)
#pragma unroll
                for (int nf = 0; nf < 8; nf++)
                    mma_tf32(acc[mf][nf], af[mf], &bf[nf >> 1][(nf & 1) << 1]);
        }
    }

    int row0 = (blockIdx.y << 7) + wm + g;
    int col0 = (blockIdx.x << 7) + wn + (tg << 1);
#pragma unroll
    for (int mf = 0; mf < 4; mf++) {
#pragma unroll
        for (int nf = 0; nf < 8; nf++) {
            size_t r = (size_t)(row0 + (mf << 4));
            int c = col0 + (nf << 3);
            float2 v0 = make_float2(acc[mf][nf][0], acc[mf][nf][1]);
            float2 v1 = make_float2(acc[mf][nf][2], acc[mf][nf][3]);
            *reinterpret_cast<float2*>(Zg + r * 4096 + c) = v0;
            *reinterpret_cast<float2*>(Zg + (r + 8) * 4096 + c) = v1;
        }
    }
}

// ---------------- launch ----------------
extern "C" void kernel_launch(void* const* d_in, const int* in_sizes, int n_in,
                              void* d_out, int out_size) {
    const float* input   = (const float*)d_in[0];
    const int*   Qidxs   = (const int*)d_in[1];
    const float* cb      = (const float*)d_in[2];
    const float* SU      = (const float*)d_in[3];
    const float* SV      = (const float*)d_in[4];
    const float* A       = (const float*)d_in[5];
    const float* B       = (const float*)d_in[6];
    const float* scaleWH = (const float*)d_in[7];
    const float* bias    = (const float*)d_in[8];
    float* out = (float*)d_out;

    static bool attr_done = false;
    if (!attr_done) {
        bool ok1 = cudaFuncSetAttribute(gemm_nt, cudaFuncAttributeMaxDynamicSharedMemorySize,
                                        GEMM_SMEM) == cudaSuccess;
        bool ok2 = cudaFuncSetAttribute(zgemm_big, cudaFuncAttributeMaxDynamicSharedMemorySize,
                                        Z2_SMEM) == cudaSuccess;
        bool ok3 = cudaFuncSetAttribute(xb_mma, cudaFuncAttributeMaxDynamicSharedMemorySize,
                                        XBM_SMEM) == cudaSuccess;
        if (ok1 && ok2 && ok3) attr_done = true;
    }

    static float *X = nullptr, *W = nullptr, *Z = nullptr, *ABX = nullptr,
                 *XB = nullptr, *AQ = nullptr;
    if (!X) {
        cudaGetSymbolAddress((void**)&X,   g_X);
        cudaGetSymbolAddress((void**)&W,   g_W);
        cudaGetSymbolAddress((void**)&Z,   g_Z);
        cudaGetSymbolAddress((void**)&ABX, g_ABX);
        cudaGetSymbolAddress((void**)&XB,  g_XB);
        cudaGetSymbolAddress((void**)&AQ,  g_AQ);
    }

    // One side stream + fork/join events (created once on the first, uncaptured,
    // call; record/wait are graph-capturable and become graph edges).
    static cudaStream_t s1 = nullptr;
    static cudaEvent_t ev0 = nullptr, evD = nullptr, evA = nullptr, evC = nullptr;
    static int streams_ok = -1;
    if (streams_ok < 0) {
        bool ok = cudaStreamCreateWithFlags(&s1, cudaStreamNonBlocking) == cudaSuccess;
        ok = ok && cudaEventCreateWithFlags(&ev0, cudaEventDisableTiming) == cudaSuccess;
        ok = ok && cudaEventCreateWithFlags(&evD, cudaEventDisableTiming) == cudaSuccess;
        ok = ok && cudaEventCreateWithFlags(&evA, cudaEventDisableTiming) == cudaSuccess;
        ok = ok && cudaEventCreateWithFlags(&evC, cudaEventDisableTiming) == cudaSuccess;
        streams_ok = ok ? 1 : 0;
    }

    if (streams_ok == 1) {
        // fork: side stream joins capture via ev0
        cudaEventRecord(ev0, 0);
        cudaStreamWaitEvent(s1, ev0, 0);
        // s1: dequant + round_a (independent of fwht_pre)
        dequant_kernel<<<(OUT_F * (IN_F / 8)) / 256, 256, 0, s1>>>(Qidxs, cb);
        round_a_kernel<<<(OUT_F * RANK) / 256, 256, 0, s1>>>(A);
        cudaEventRecord(evD, s1);
        // s0: scale + FWHT of input
        c1_kernel<<<16, 256>>>(SU, scaleWH);
        fwht_pre<<<NTOK, 512>>>(input);
        cudaEventRecord(evA, 0);
        // s0: big GEMM needs W (evD)
        cudaStreamWaitEvent(0, evD, 0);
        zgemm_big<<<dim3(32, 64), 128, Z2_SMEM>>>(X, W, Z);
        // s1: low-rank chain needs X (evA); runs under zgemm
        cudaStreamWaitEvent(s1, evA, 0);
        xb_mma<<<dim3(64, 8), 128, XBM_SMEM, s1>>>(B);
        xb_reduce<<<(NTOK * RANK) / 256, 256, 0, s1>>>();
        gemm_nt<<<dim3(32, 64), 256, GEMM_SMEM, s1>>>(XB, AQ, ABX, RANK);
        cudaEventRecord(evC, s1);
        // s0: epilogue needs Z (program order) + ABX (evC)
        cudaStreamWaitEvent(0, evC, 0);
        fwht_post<<<NTOK, 512>>>(SV, bias, out);
    } else {
        // serial fallback (identical to R14)
        c1_kernel<<<16, 256>>>(SU, scaleWH);
        fwht_pre<<<NTOK, 512>>>(input);
        dequant_kernel<<<(OUT_F * (IN_F / 8)) / 256, 256>>>(Qidxs, cb);
        zgemm_big<<<dim3(32, 64), 128, Z2_SMEM>>>(X, W, Z);
        round_a_kernel<<<(OUT_F * RANK) / 256, 256>>>(A);
        xb_mma<<<dim3(64, 8), 128, XBM_SMEM>>>(B);
        xb_reduce<<<(NTOK * RANK) / 256, 256>>>();
        gemm_nt<<<dim3(32, 64), 256, GEMM_SMEM>>>(XB, AQ, ABX, RANK);
        fwht_post<<<NTOK, 512>>>(SV, bias, out);
    }
}

// round 16
// speedup vs baseline: 1.2300x; 1.0066x over previous
#include <cuda_runtime.h>
#include <cstdint>

#define IN_F  4096
#define OUT_F 4096
#define NTOK  8192
#define RANK  64

// ---------------- scratch (static device globals; no allocation) ----------------
__device__ float g_X  [(size_t)NTOK * IN_F];    // fwht'd, scaled, tf32-rounded input
__device__ float g_W  [(size_t)OUT_F * IN_F];   // dequantized codebook weights (tf32-rounded)
__device__ float g_Z  [(size_t)NTOK * OUT_F];   // x @ W^T
__device__ float g_ABX[(size_t)NTOK * OUT_F];   // (x B^T) A^T
__device__ float g_XB [NTOK * RANK];            // x @ B^T (tf32-rounded)
__device__ float g_XBp[8 * NTOK * RANK];        // split-K partials for XB (8 splits)
__device__ float g_AQ [OUT_F * RANK];           // tf32-rounded A
__device__ float g_C1 [IN_F];                   // SU / scaleWH

// ---------------- helpers ----------------
__device__ __forceinline__ float tf32r(float f) {
    uint32_t u;
    asm("cvt.rna.tf32.f32 %0, %1;" : "=r"(u) : "f"(f));
    return __uint_as_float(u);
}

#define BFLY(a, b) do { float _u = (a); float _v = (b); (a) = _u + _v; (b) = _u - _v; } while (0)

__device__ __forceinline__ void h8(float e[8]) {
    BFLY(e[0], e[1]); BFLY(e[2], e[3]); BFLY(e[4], e[5]); BFLY(e[6], e[7]);
    BFLY(e[0], e[2]); BFLY(e[1], e[3]); BFLY(e[4], e[6]); BFLY(e[5], e[7]);
    BFLY(e[0], e[4]); BFLY(e[1], e[5]); BFLY(e[2], e[6]); BFLY(e[3], e[7]);
}

// 12-stage 4096-pt FWHT core over v[4][4] held by 256 threads.
// idx(q,c) = q*1024 + tid*4 + c. Stages: regs (bits 0,1,10,11), shfl (bits 2-6).
__device__ __forceinline__ void fwht_core_regs(float v[4][4], int lane) {
    // bits 0-1 (c)
#pragma unroll
    for (int q = 0; q < 4; q++) {
        BFLY(v[q][0], v[q][1]); BFLY(v[q][2], v[q][3]);
        BFLY(v[q][0], v[q][2]); BFLY(v[q][1], v[q][3]);
    }
    // bits 10-11 (q)
#pragma unroll
    for (int c = 0; c < 4; c++) {
        BFLY(v[0][c], v[1][c]); BFLY(v[2][c], v[3][c]);
        BFLY(v[0][c], v[2][c]); BFLY(v[1][c], v[3][c]);
    }
    // bits 2-6 via shuffle butterflies
#pragma unroll
    for (int m = 0; m < 5; m++) {
        int mask = 1 << m;
        float sgn = (lane & mask) ? -1.f : 1.f;
#pragma unroll
        for (int q = 0; q < 4; q++)
#pragma unroll
            for (int c = 0; c < 4; c++) {
                float o = __shfl_xor_sync(0xffffffffu, v[q][c], mask);
                v[q][c] = fmaf(sgn, v[q][c], o);
            }
    }
}

// ---------------- tiny prep kernels ----------------
__global__ void c1_kernel(const float* __restrict__ SU, const float* __restrict__ sWH) {
    int i = blockIdx.x * 256 + threadIdx.x;
    if (i < IN_F) g_C1[i] = SU[i] / sWH[i];
}

__global__ void round_a_kernel(const float* __restrict__ A) {
    int i = blockIdx.x * 256 + threadIdx.x;
    if (i < OUT_F * RANK) g_AQ[i] = tf32r(A[i]);
}

// ---------------- dequant: W[m][k] = cb[Q[m][k/8]][k%8], tf32-rounded ----------------
__global__ void dequant_kernel(const int* __restrict__ Q, const float* __restrict__ cb) {
    int i = blockIdx.x * 256 + threadIdx.x;            // 0 .. 4096*512
    if (i >= OUT_F * (IN_F / 8)) return;
    int q = Q[i];
    const float4* c = reinterpret_cast<const float4*>(cb) + ((size_t)q << 1);
    float4 v0 = c[0], v1 = c[1];
    float4 r0, r1;
    r0.x = tf32r(v0.x); r0.y = tf32r(v0.y); r0.z = tf32r(v0.z); r0.w = tf32r(v0.w);
    r1.x = tf32r(v1.x); r1.y = tf32r(v1.y); r1.z = tf32r(v1.z); r1.w = tf32r(v1.w);
    float4* w = reinterpret_cast<float4*>(g_W) + ((size_t)i << 1);
    w[0] = r0; w[1] = r1;
}

// ---------------- FWHT pre: X = fwht(input * C1) / 64, tf32-rounded ----------------
__global__ void __launch_bounds__(256) fwht_pre(const float* __restrict__ in) {
    __shared__ float s[4096];
    int row = blockIdx.x, tid = threadIdx.x, lane = tid & 31;
    const float* src = in + (size_t)row * IN_F;
    float v[4][4];
#pragma unroll
    for (int q = 0; q < 4; q++) {
        float4 x = *reinterpret_cast<const float4*>(src + q * 1024 + tid * 4);
        float4 c = *reinterpret_cast<const float4*>(g_C1 + q * 1024 + tid * 4);
        v[q][0] = x.x * c.x; v[q][1] = x.y * c.y;
        v[q][2] = x.z * c.z; v[q][3] = x.w * c.w;
    }
    fwht_core_regs(v, lane);
#pragma unroll
    for (int q = 0; q < 4; q++)
        *reinterpret_cast<float4*>(s + q * 1024 + tid * 4) =
            make_float4(v[q][0], v[q][1], v[q][2], v[q][3]);
    __syncthreads();
    // bits 7-9 via one smem exchange; outputs coalesced
    float* dst = g_X + (size_t)row * IN_F;
#pragma unroll
    for (int j = 0; j < 2; j++) {
        int base = ((j << 1) + (tid >> 7)) * 1024 + (tid & 127);
        float e[8];
#pragma unroll
        for (int i = 0; i < 8; i++) e[i] = s[base + i * 128];
        h8(e);
#pragma unroll
        for (int i = 0; i < 8; i++) dst[base + i * 128] = tf32r(e[i] * 0.015625f);
    }
}

// ---------------- FWHT post + epilogue: out = (fwht(Z)/64 + ABX)*SV + bias ----------------
__global__ void __launch_bounds__(256) fwht_post(const float* __restrict__ SV,
                                                 const float* __restrict__ bias,
                                                 float* __restrict__ out) {
    __shared__ float s[4096];
    int row = blockIdx.x, tid = threadIdx.x, lane = tid & 31;
    const float* src = g_Z + (size_t)row * OUT_F;
    float v[4][4];
#pragma unroll
    for (int q = 0; q < 4; q++) {
        float4 x = *reinterpret_cast<const float4*>(src + q * 1024 + tid * 4);
        v[q][0] = x.x; v[q][1] = x.y; v[q][2] = x.z; v[q][3] = x.w;
    }
    fwht_core_regs(v, lane);
#pragma unroll
    for (int q = 0; q < 4; q++)
        *reinterpret_cast<float4*>(s + q * 1024 + tid * 4) =
            make_float4(v[q][0], v[q][1], v[q][2], v[q][3]);
    __syncthreads();
    const float* abx = g_ABX + (size_t)row * OUT_F;
    float* dst = out + (size_t)row * OUT_F;
#pragma unroll
    for (int j = 0; j < 2; j++) {
        int base = ((j << 1) + (tid >> 7)) * 1024 + (tid & 127);
        float e[8];
#pragma unroll
        for (int i = 0; i < 8; i++) e[i] = s[base + i * 128];
        h8(e);
#pragma unroll
        for (int i = 0; i < 8; i++) {
            int idx = base + i * 128;
            dst[idx] = (e[i] * 0.015625f + abx[idx]) * SV[idx] + bias[idx];
        }
    }
}

// ---------------- shared HMMA helpers ----------------
__device__ __forceinline__ void mma_tf32(float* c, const uint32_t* a, const uint32_t* b) {
    asm volatile(
        "mma.sync.aligned.m16n8k8.row.col.f32.tf32.tf32.f32 "
        "{%0,%1,%2,%3}, {%4,%5,%6,%7}, {%8,%9}, {%0,%1,%2,%3};\n"
        : "+f"(c[0]), "+f"(c[1]), "+f"(c[2]), "+f"(c[3])
        : "r"(a[0]), "r"(a[1]), "r"(a[2]), "r"(a[3]), "r"(b[0]), "r"(b[1]));
}

__device__ __forceinline__ void cp16(uint32_t s, const void* g) {
    asm volatile("cp.async.cg.shared.global [%0], [%1], 16;\n" :: "r"(s), "l"(g) : "memory");
}

__device__ __forceinline__ void ldsm4(uint32_t& r0, uint32_t& r1, uint32_t& r2, uint32_t& r3,
                                      uint32_t addr) {
    asm volatile("ldmatrix.sync.aligned.m8n8.x4.shared.b16 {%0,%1,%2,%3}, [%4];"
                 : "=r"(r0), "=r"(r1), "=r"(r2), "=r"(r3) : "r"(addr));
}

// =================================================================================
// XB = X @ B^T via tf32 MMA split-K: M=8192, N=64, K=4096 split 8 x 512.
// =================================================================================
#define XBM_AF   (128 * 36)
#define XBM_BF   (64 * 36)
#define XBM_STG  (XBM_AF + XBM_BF)          // 6912 floats = 27648 B
#define XBM_SMEM (3 * XBM_STG * 4)          // 82944 B
#define XBM_KIT  16

__device__ __forceinline__ void xbm_load(uint32_t sb, int buf, int it,
                                         const float* Ag, const float* Bg, int tid) {
    int k0 = it << 5;
    uint32_t sA = sb + (uint32_t)buf * (XBM_STG * 4);
    uint32_t sB = sA + XBM_AF * 4;
#pragma unroll
    for (int i = 0; i < 8; i++) {            // A: 1024 float4 over 128 threads
        int idx = tid + (i << 7);
        int r = idx >> 3, c4 = (idx & 7) << 2;
        cp16(sA + (uint32_t)(r * 36 + c4) * 4u, Ag + (size_t)r * IN_F + k0 + c4);
    }
#pragma unroll
    for (int i = 0; i < 4; i++) {            // B: 512 float4
        int idx = tid + (i << 7);
        int r = idx >> 3, c4 = (idx & 7) << 2;
        cp16(sB + (uint32_t)(r * 36 + c4) * 4u, Bg + (size_t)r * IN_F + k0 + c4);
    }
    asm volatile("cp.async.commit_group;\n" ::: "memory");
}

__global__ void __launch_bounds__(128, 2) xb_mma(const float* __restrict__ B) {
    extern __shared__ float sm[];
    uint32_t sb = (uint32_t)__cvta_generic_to_shared(sm);
    int tid = threadIdx.x;
    int lane = tid & 31, wid = tid >> 5;
    int g = lane >> 2, tg = lane & 3;
    int wm = wid << 5;                        // warp m offset: 4 warps x 32 rows

    int bm = blockIdx.x;                      // 0..63
    int ks = blockIdx.y;                      // 0..7
    const float* Ag = g_X + (size_t)bm * 128 * IN_F + (ks << 9);
    const float* Bg = B + (ks << 9);

    uint32_t aoff = ((uint32_t)(wm + (((lane >> 3) & 1) << 3) + (lane & 7)) * 36u
                     + (uint32_t)((lane >> 4) << 2)) * 4u;
    uint32_t boff = ((uint32_t)(((lane >> 4) << 3) + (lane & 7)) * 36u
                     + (uint32_t)(((lane >> 3) & 1) << 2)) * 4u;

    xbm_load(sb, 0, 0, Ag, Bg, tid);
    xbm_load(sb, 1, 1, Ag, Bg, tid);

    float acc[2][8][4];
#pragma unroll
    for (int a = 0; a < 2; a++)
#pragma unroll
        for (int b = 0; b < 8; b++)
#pragma unroll
            for (int c = 0; c < 4; c++) acc[a][b][c] = 0.f;

    for (int it = 0; it < XBM_KIT; it++) {
        int b = it % 3;
        if (it == XBM_KIT - 1) asm volatile("cp.async.wait_group 0;\n" ::: "memory");
        else                   asm volatile("cp.async.wait_group 1;\n" ::: "memory");
        __syncthreads();

        if (it + 2 < XBM_KIT) xbm_load(sb, (it + 2) % 3, it + 2, Ag, Bg, tid);

        uint32_t sAb = sb + (uint32_t)b * (XBM_STG * 4) + aoff;
        uint32_t sBb = sb + (uint32_t)b * (XBM_STG * 4) + XBM_AF * 4 + boff;
#pragma unroll
        for (int ksu = 0; ksu < 4; ksu++) {
            uint32_t af[2][4], bf[4][4];
#pragma unroll
            for (int mf = 0; mf < 2; mf++)
                ldsm4(af[mf][0], af[mf][1], af[mf][2], af[mf][3],
                      sAb + (uint32_t)(mf * 2304 + ksu * 32));
#pragma unroll
            for (int nfp = 0; nfp < 4; nfp++)
                ldsm4(bf[nfp][0], bf[nfp][1], bf[nfp][2], bf[nfp][3],
                      sBb + (uint32_t)(nfp * 2304 + ksu * 32));
#pragma unroll
            for (int mf = 0; mf < 2; mf++)
#pragma unroll
                for (int nf = 0; nf < 8; nf++)
                    mma_tf32(acc[mf][nf], af[mf], &bf[nf >> 1][(nf & 1) << 1]);
        }
    }

    const size_t S = (size_t)NTOK * RANK;
    int row0 = bm * 128 + wm + g;
    int col0 = tg << 1;
    float* dstb = g_XBp + (size_t)ks * S;
#pragma unroll
    for (int mf = 0; mf < 2; mf++) {
#pragma unroll
        for (int nf = 0; nf < 8; nf++) {
            int r = row0 + (mf << 4);
            int c = col0 + (nf << 3);
            float2 v0 = make_float2(acc[mf][nf][0], acc[mf][nf][1]);
            float2 v1 = make_float2(acc[mf][nf][2], acc[mf][nf][3]);
            *reinterpret_cast<float2*>(dstb + (size_t)r * RANK + c) = v0;
            *reinterpret_cast<float2*>(dstb + (size_t)(r + 8) * RANK + c) = v1;
        }
    }
}

__global__ void xb_reduce() {
    int i = blockIdx.x * 256 + threadIdx.x;   // < 524288
    const size_t S = (size_t)NTOK * RANK;
    float s = 0.f;
#pragma unroll
    for (int k = 0; k < 8; k++) s += g_XBp[(size_t)k * S + i];
    g_XB[i] = tf32r(s);
}

// ---------------- small HMMA tf32 GEMM (ABX, K=64): 128x128 tiles ----------------
__device__ __forceinline__ void load_tile(const float* g, int ldg, uint32_t sbase, int tid) {
    int r = tid >> 3;
    int c4 = (tid & 7) << 2;
#pragma unroll
    for (int i = 0; i < 4; i++) {
        int row = r + (i << 5);
        cp16(sbase + (uint32_t)(row * 36 + c4) * 4u, g + (size_t)row * ldg + c4);
    }
}

#define GEMM_TB (128 * 36)
#define GEMM_SMEM (4 * GEMM_TB * 4)

__global__ void __launch_bounds__(256, 2) gemm_nt(const float* __restrict__ A,
                                                  const float* __restrict__ Bm,
                                                  float* __restrict__ C, int K) {
    extern __shared__ float sm[];
    uint32_t sA = (uint32_t)__cvta_generic_to_shared(sm);
    uint32_t sB = sA + 2u * GEMM_TB * 4u;
    int tid = threadIdx.x;
    const float* Ag = A + (size_t)(blockIdx.y * 128) * K;
    const float* Bg = Bm + (size_t)(blockIdx.x * 128) * K;
    int KIT = K >> 5;

    load_tile(Ag, K, sA, tid);
    load_tile(Bg, K, sB, tid);
    asm volatile("cp.async.commit_group;\n" ::: "memory");

    int lane = tid & 31, wid = tid >> 5;
    int g = lane >> 2, tg = lane & 3;
    int wm = (wid & 1) << 6;
    int wn = (wid >> 1) << 5;

    float acc[4][4][4];
#pragma unroll
    for (int a = 0; a < 4; a++)
#pragma unroll
        for (int b = 0; b < 4; b++)
#pragma unroll
            for (int c = 0; c < 4; c++) acc[a][b][c] = 0.f;

    const float* As = sm;
    const float* Bs = sm + 2 * GEMM_TB;

    for (int it = 0; it < KIT; it++) {
        if (it + 1 < KIT) {
            uint32_t nb = ((it + 1) & 1) ? (uint32_t)(GEMM_TB * 4) : 0u;
            load_tile(Ag + (it + 1) * 32, K, sA + nb, tid);
            load_tile(Bg + (it + 1) * 32, K, sB + nb, tid);
            asm volatile("cp.async.commit_group;\n" ::: "memory");
            asm volatile("cp.async.wait_group 1;\n" ::: "memory");
        } else {
            asm volatile("cp.async.wait_group 0;\n" ::: "memory");
        }
        __syncthreads();
        const float* Ac = As + (it & 1) * GEMM_TB;
        const float* Bc = Bs + (it & 1) * GEMM_TB;
#pragma unroll
        for (int ksu = 0; ksu < 4; ksu++) {
            int kc = ksu << 3;
            uint32_t af[4][4], bf[4][2];
#pragma unroll
            for (int mf = 0; mf < 4; mf++) {
                int r0 = wm + (mf << 4) + g;
                af[mf][0] = __float_as_uint(Ac[r0 * 36 + kc + tg]);
                af[mf][1] = __float_as_uint(Ac[(r0 + 8) * 36 + kc + tg]);
                af[mf][2] = __float_as_uint(Ac[r0 * 36 + kc + tg + 4]);
                af[mf][3] = __float_as_uint(Ac[(r0 + 8) * 36 + kc + tg + 4]);
            }
#pragma unroll
            for (int nf = 0; nf < 4; nf++) {
                int n0 = wn + (nf << 3) + g;
                bf[nf][0] = __float_as_uint(Bc[n0 * 36 + kc + tg]);
                bf[nf][1] = __float_as_uint(Bc[n0 * 36 + kc + tg + 4]);
            }
#pragma unroll
            for (int mf = 0; mf < 4; mf++)
#pragma unroll
                for (int nf = 0; nf < 4; nf++)
                    mma_tf32(acc[mf][nf], af[mf], bf[nf]);
        }
        __syncthreads();
    }

    int row0 = (blockIdx.y << 7) + wm + g;
    int col0 = (blockIdx.x << 7) + wn + (tg << 1);
#pragma unroll
    for (int mf = 0; mf < 4; mf++) {
#pragma unroll
        for (int nf = 0; nf < 4; nf++) {
            size_t r = (size_t)(row0 + (mf << 4));
            int c = col0 + (nf << 3);
            float2 v0 = make_float2(acc[mf][nf][0], acc[mf][nf][1]);
            float2 v1 = make_float2(acc[mf][nf][2], acc[mf][nf][3]);
            *reinterpret_cast<float2*>(C + r * 4096 + c) = v0;
            *reinterpret_cast<float2*>(C + (r + 8) * 4096 + c) = v1;
        }
    }
}

// =================================================================================
// Big HMMA tf32 GEMM: Z[8192,4096] = X @ W^T  — exact R10 best config.
// =================================================================================
#define Z2_TF   (128 * 36)                 // floats per (A or B) stage tile
#define Z2_STG  (2 * Z2_TF)                // 9216 floats = 36864 B per stage
#define Z2_SMEM (3 * Z2_STG * 4)           // 110592 B
#define Z2_KIT  128

__device__ __forceinline__ void z2_load(uint32_t sb, int buf, int it,
                                        const float* Ag, const float* Bg, int tid) {
    int k0 = it << 5;
    uint32_t sA = sb + (uint32_t)buf * (Z2_STG * 4);
    uint32_t sB = sA + Z2_TF * 4;
#pragma unroll
    for (int i = 0; i < 8; i++) {           // A: 1024 float4 over 128 threads
        int idx = tid + (i << 7);
        int r = idx >> 3, c4 = (idx & 7) << 2;
        cp16(sA + (uint32_t)(r * 36 + c4) * 4u, Ag + (size_t)r * IN_F + k0 + c4);
    }
#pragma unroll
    for (int i = 0; i < 8; i++) {           // B: 1024 float4
        int idx = tid + (i << 7);
        int r = idx >> 3, c4 = (idx & 7) << 2;
        cp16(sB + (uint32_t)(r * 36 + c4) * 4u, Bg + (size_t)r * IN_F + k0 + c4);
    }
    asm volatile("cp.async.commit_group;\n" ::: "memory");
}

__global__ void __launch_bounds__(128, 2) zgemm_big(const float* __restrict__ Xg,
                                                    const float* __restrict__ Wg,
                                                    float* __restrict__ Zg) {
    extern __shared__ float sm[];
    uint32_t sb = (uint32_t)__cvta_generic_to_shared(sm);
    int tid = threadIdx.x;
    int lane = tid & 31, wid = tid >> 5;   // 4 warps
    int g = lane >> 2, tg = lane & 3;
    int wm = (wid & 1) << 6;        // 2 warps in m -> 128
    int wn = (wid >> 1) << 6;       // 2 warps in n -> 128 (64 cols each)

    const float* Ag = Xg + (size_t)blockIdx.y * 128 * IN_F;
    const float* Bg = Wg + (size_t)blockIdx.x * 128 * IN_F;

    uint32_t aoff = ((uint32_t)(wm + (((lane >> 3) & 1) << 3) + (lane & 7)) * 36u
                     + (uint32_t)((lane >> 4) << 2)) * 4u;
    uint32_t boff = ((uint32_t)(wn + ((lane >> 4) << 3) + (lane & 7)) * 36u
                     + (uint32_t)(((lane >> 3) & 1) << 2)) * 4u;

    z2_load(sb, 0, 0, Ag, Bg, tid);
    z2_load(sb, 1, 1, Ag, Bg, tid);

    float acc[4][8][4];                    // 64x64 warp tile: 4 m-frags x 8 n-frags
#pragma unroll
    for (int a = 0; a < 4; a++)
#pragma unroll
        for (int b = 0; b < 8; b++)
#pragma unroll
            for (int c = 0; c < 4; c++) acc[a][b][c] = 0.f;

    for (int it = 0; it < Z2_KIT; it++) {
        int b = it % 3;
        if (it == Z2_KIT - 1) asm volatile("cp.async.wait_group 0;\n" ::: "memory");
        else                  asm volatile("cp.async.wait_group 1;\n" ::: "memory");
        __syncthreads();   // all warps done computing iter it-1 -> slot (it+2)%3 free

        if (it + 2 < Z2_KIT) z2_load(sb, (it + 2) % 3, it + 2, Ag, Bg, tid);

        uint32_t sAb = sb + (uint32_t)b * (Z2_STG * 4) + aoff;
        uint32_t sBb = sb + (uint32_t)b * (Z2_STG * 4) + Z2_TF * 4 + boff;
#pragma unroll
        for (int ksu = 0; ksu < 4; ksu++) {
            uint32_t af[4][4], bf[4][4];
#pragma unroll
            for (int mf = 0; mf < 4; mf++)
                ldsm4(af[mf][0], af[mf][1], af[mf][2], af[mf][3],
                      sAb + (uint32_t)(mf * 2304 + ksu * 32));   // 16*36*4=2304
#pragma unroll
            for (int nfp = 0; nfp < 4; nfp++)
                ldsm4(bf[nfp][0], bf[nfp][1], bf[nfp][2], bf[nfp][3],
                      sBb + (uint32_t)(nfp * 2304 + ksu * 32));
#pragma unroll
            for (int mf = 0; mf < 4; mf++)
#pragma unroll
                for (int nf = 0; nf < 8; nf++)
                    mma_tf32(acc[mf][nf], af[mf], &bf[nf >> 1][(nf & 1) << 1]);
        }
    }

    int row0 = (blockIdx.y << 7) + wm + g;
    int col0 = (blockIdx.x << 7) + wn + (tg << 1);
#pragma unroll
    for (int mf = 0; mf < 4; mf++) {
#pragma unroll
        for (int nf = 0; nf < 8; nf++) {
            size_t r = (size_t)(row0 + (mf << 4));
            int c = col0 + (nf << 3);
            float2 v0 = make_float2(acc[mf][nf][0], acc[mf][nf][1]);
            float2 v1 = make_float2(acc[mf][nf][2], acc[mf][nf][3]);
            *reinterpret_cast<float2*>(Zg + r * 4096 + c) = v0;
            *reinterpret_cast<float2*>(Zg + (r + 8) * 4096 + c) = v1;
        }
    }
}

// ---------------- launch ----------------
extern "C" void kernel_launch(void* const* d_in, const int* in_sizes, int n_in,
                              void* d_out, int out_size) {
    const float* input   = (const float*)d_in[0];
    const int*   Qidxs   = (const int*)d_in[1];
    const float* cb      = (const float*)d_in[2];
    const float* SU      = (const float*)d_in[3];
    const float* SV      = (const float*)d_in[4];
    const float* A       = (const float*)d_in[5];
    const float* B       = (const float*)d_in[6];
    const float* scaleWH = (const float*)d_in[7];
    const float* bias    = (const float*)d_in[8];
    float* out = (float*)d_out;

    static bool attr_done = false;
    if (!attr_done) {
        bool ok1 = cudaFuncSetAttribute(gemm_nt, cudaFuncAttributeMaxDynamicSharedMemorySize,
                                        GEMM_SMEM) == cudaSuccess;
        bool ok2 = cudaFuncSetAttribute(zgemm_big, cudaFuncAttributeMaxDynamicSharedMemorySize,
                                        Z2_SMEM) == cudaSuccess;
        bool ok3 = cudaFuncSetAttribute(xb_mma, cudaFuncAttributeMaxDynamicSharedMemorySize,
                                        XBM_SMEM) == cudaSuccess;
        if (ok1 && ok2 && ok3) attr_done = true;
    }

    static float *X = nullptr, *W = nullptr, *Z = nullptr, *ABX = nullptr,
                 *XB = nullptr, *AQ = nullptr;
    if (!X) {
        cudaGetSymbolAddress((void**)&X,   g_X);
        cudaGetSymbolAddress((void**)&W,   g_W);
        cudaGetSymbolAddress((void**)&Z,   g_Z);
        cudaGetSymbolAddress((void**)&ABX, g_ABX);
        cudaGetSymbolAddress((void**)&XB,  g_XB);
        cudaGetSymbolAddress((void**)&AQ,  g_AQ);
    }

    static cudaStream_t s1 = nullptr;
    static cudaEvent_t ev0 = nullptr, evD = nullptr, evA = nullptr, evC = nullptr;
    static int streams_ok = -1;
    if (streams_ok < 0) {
        bool ok = cudaStreamCreateWithFlags(&s1, cudaStreamNonBlocking) == cudaSuccess;
        ok = ok && cudaEventCreateWithFlags(&ev0, cudaEventDisableTiming) == cudaSuccess;
        ok = ok && cudaEventCreateWithFlags(&evD, cudaEventDisableTiming) == cudaSuccess;
        ok = ok && cudaEventCreateWithFlags(&evA, cudaEventDisableTiming) == cudaSuccess;
        ok = ok && cudaEventCreateWithFlags(&evC, cudaEventDisableTiming) == cudaSuccess;
        streams_ok = ok ? 1 : 0;
    }

    if (streams_ok == 1) {
        cudaEventRecord(ev0, 0);
        cudaStreamWaitEvent(s1, ev0, 0);
        dequant_kernel<<<(OUT_F * (IN_F / 8)) / 256, 256, 0, s1>>>(Qidxs, cb);
        round_a_kernel<<<(OUT_F * RANK) / 256, 256, 0, s1>>>(A);
        cudaEventRecord(evD, s1);
        c1_kernel<<<16, 256>>>(SU, scaleWH);
        fwht_pre<<<NTOK, 256>>>(input);
        cudaEventRecord(evA, 0);
        cudaStreamWaitEvent(0, evD, 0);
        zgemm_big<<<dim3(32, 64), 128, Z2_SMEM>>>(X, W, Z);
        cudaStreamWaitEvent(s1, evA, 0);
        xb_mma<<<dim3(64, 8), 128, XBM_SMEM, s1>>>(B);
        xb_reduce<<<(NTOK * RANK) / 256, 256, 0, s1>>>();
        gemm_nt<<<dim3(32, 64), 256, GEMM_SMEM, s1>>>(XB, AQ, ABX, RANK);
        cudaEventRecord(evC, s1);
        cudaStreamWaitEvent(0, evC, 0);
        fwht_post<<<NTOK, 256>>>(SV, bias, out);
    } else {
        c1_kernel<<<16, 256>>>(SU, scaleWH);
        fwht_pre<<<NTOK, 256>>>(input);
        dequant_kernel<<<(OUT_F * (IN_F / 8)) / 256, 256>>>(Qidxs, cb);
        zgemm_big<<<dim3(32, 64), 128, Z2_SMEM>>>(X, W, Z);
        round_a_kernel<<<(OUT_F * RANK) / 256, 256>>>(A);
        xb_mma<<<dim3(64, 8), 128, XBM_SMEM>>>(B);
        xb_reduce<<<(NTOK * RANK) / 256, 256>>>();
        gemm_nt<<<dim3(32, 64), 256, GEMM_SMEM>>>(XB, AQ, ABX, RANK);
        fwht_post<<<NTOK, 256>>>(SV, bias, out);
    }
}

// round 17
// speedup vs baseline: 1.2984x; 1.0556x over previous
#include <cuda_runtime.h>
#include <cstdint>

#define IN_F  4096
#define OUT_F 4096
#define NTOK  8192
#define RANK  64

// ---------------- scratch (static device globals; no allocation) ----------------
__device__ float g_X  [(size_t)NTOK * IN_F];
__device__ float g_W  [(size_t)OUT_F * IN_F];
__device__ float g_Z  [(size_t)NTOK * OUT_F];
__device__ float g_ABX[(size_t)NTOK * OUT_F];
__device__ float g_XB [NTOK * RANK];
__device__ float g_XBp[8 * NTOK * RANK];
__device__ float g_AQ [OUT_F * RANK];
__device__ float g_C1 [IN_F];

// ---------------- helpers ----------------
__device__ __forceinline__ float tf32r(float f) {
    uint32_t u;
    asm("cvt.rna.tf32.f32 %0, %1;" : "=r"(u) : "f"(f));
    return __uint_as_float(u);
}

#define BFLY(a, b) do { float _u = (a); float _v = (b); (a) = _u + _v; (b) = _u - _v; } while (0)

__device__ __forceinline__ void h8(float e[8]) {
    BFLY(e[0], e[1]); BFLY(e[2], e[3]); BFLY(e[4], e[5]); BFLY(e[6], e[7]);
    BFLY(e[0], e[2]); BFLY(e[1], e[3]); BFLY(e[4], e[6]); BFLY(e[5], e[7]);
    BFLY(e[0], e[4]); BFLY(e[1], e[5]); BFLY(e[2], e[6]); BFLY(e[3], e[7]);
}

// 12-stage 4096-pt FWHT core over v[4][4] held by 256 threads.
__device__ __forceinline__ void fwht_core_regs(float v[4][4], int lane) {
#pragma unroll
    for (int q = 0; q < 4; q++) {
        BFLY(v[q][0], v[q][1]); BFLY(v[q][2], v[q][3]);
        BFLY(v[q][0], v[q][2]); BFLY(v[q][1], v[q][3]);
    }
#pragma unroll
    for (int c = 0; c < 4; c++) {
        BFLY(v[0][c], v[1][c]); BFLY(v[2][c], v[3][c]);
        BFLY(v[0][c], v[2][c]); BFLY(v[1][c], v[3][c]);
    }
#pragma unroll
    for (int m = 0; m < 5; m++) {
        int mask = 1 << m;
        float sgn = (lane & mask) ? -1.f : 1.f;
#pragma unroll
        for (int q = 0; q < 4; q++)
#pragma unroll
            for (int c = 0; c < 4; c++) {
                float o = __shfl_xor_sync(0xffffffffu, v[q][c], mask);
                v[q][c] = fmaf(sgn, v[q][c], o);
            }
    }
}

// ---------------- tiny prep kernels ----------------
__global__ void c1_kernel(const float* __restrict__ SU, const float* __restrict__ sWH) {
    int i = blockIdx.x * 256 + threadIdx.x;
    if (i < IN_F) g_C1[i] = SU[i] / sWH[i];
}

__global__ void round_a_kernel(const float* __restrict__ A) {
    int i = blockIdx.x * 256 + threadIdx.x;
    if (i < OUT_F * RANK) g_AQ[i] = tf32r(A[i]);
}

__global__ void dequant_kernel(const int* __restrict__ Q, const float* __restrict__ cb) {
    int i = blockIdx.x * 256 + threadIdx.x;
    if (i >= OUT_F * (IN_F / 8)) return;
    int q = Q[i];
    const float4* c = reinterpret_cast<const float4*>(cb) + ((size_t)q << 1);
    float4 v0 = c[0], v1 = c[1];
    float4 r0, r1;
    r0.x = tf32r(v0.x); r0.y = tf32r(v0.y); r0.z = tf32r(v0.z); r0.w = tf32r(v0.w);
    r1.x = tf32r(v1.x); r1.y = tf32r(v1.y); r1.z = tf32r(v1.z); r1.w = tf32r(v1.w);
    float4* w = reinterpret_cast<float4*>(g_W) + ((size_t)i << 1);
    w[0] = r0; w[1] = r1;
}

// ---------------- FWHT pre (row-offset for half-split pipelining) ----------------
__global__ void __launch_bounds__(256) fwht_pre(const float* __restrict__ in, int row0) {
    __shared__ float s[4096];
    int row = blockIdx.x + row0, tid = threadIdx.x, lane = tid & 31;
    const float* src = in + (size_t)row * IN_F;
    float v[4][4];
#pragma unroll
    for (int q = 0; q < 4; q++) {
        float4 x = *reinterpret_cast<const float4*>(src + q * 1024 + tid * 4);
        float4 c = *reinterpret_cast<const float4*>(g_C1 + q * 1024 + tid * 4);
        v[q][0] = x.x * c.x; v[q][1] = x.y * c.y;
        v[q][2] = x.z * c.z; v[q][3] = x.w * c.w;
    }
    fwht_core_regs(v, lane);
#pragma unroll
    for (int q = 0; q < 4; q++)
        *reinterpret_cast<float4*>(s + q * 1024 + tid * 4) =
            make_float4(v[q][0], v[q][1], v[q][2], v[q][3]);
    __syncthreads();
    float* dst = g_X + (size_t)row * IN_F;
#pragma unroll
    for (int j = 0; j < 2; j++) {
        int base = ((j << 1) + (tid >> 7)) * 1024 + (tid & 127);
        float e[8];
#pragma unroll
        for (int i = 0; i < 8; i++) e[i] = s[base + i * 128];
        h8(e);
#pragma unroll
        for (int i = 0; i < 8; i++) dst[base + i * 128] = tf32r(e[i] * 0.015625f);
    }
}

// ---------------- FWHT post + epilogue (row-offset) ----------------
__global__ void __launch_bounds__(256) fwht_post(const float* __restrict__ SV,
                                                 const float* __restrict__ bias,
                                                 float* __restrict__ out, int row0) {
    __shared__ float s[4096];
    int row = blockIdx.x + row0, tid = threadIdx.x, lane = tid & 31;
    const float* src = g_Z + (size_t)row * OUT_F;
    float v[4][4];
#pragma unroll
    for (int q = 0; q < 4; q++) {
        float4 x = *reinterpret_cast<const float4*>(src + q * 1024 + tid * 4);
        v[q][0] = x.x; v[q][1] = x.y; v[q][2] = x.z; v[q][3] = x.w;
    }
    fwht_core_regs(v, lane);
#pragma unroll
    for (int q = 0; q < 4; q++)
        *reinterpret_cast<float4*>(s + q * 1024 + tid * 4) =
            make_float4(v[q][0], v[q][1], v[q][2], v[q][3]);
    __syncthreads();
    const float* abx = g_ABX + (size_t)row * OUT_F;
    float* dst = out + (size_t)row * OUT_F;
#pragma unroll
    for (int j = 0; j < 2; j++) {
        int base = ((j << 1) + (tid >> 7)) * 1024 + (tid & 127);
        float e[8];
#pragma unroll
        for (int i = 0; i < 8; i++) e[i] = s[base + i * 128];
        h8(e);
#pragma unroll
        for (int i = 0; i < 8; i++) {
            int idx = base + i * 128;
            dst[idx] = (e[i] * 0.015625f + abx[idx]) * SV[idx] + bias[idx];
        }
    }
}

// ---------------- shared HMMA helpers ----------------
__device__ __forceinline__ void mma_tf32(float* c, const uint32_t* a, const uint32_t* b) {
    asm volatile(
        "mma.sync.aligned.m16n8k8.row.col.f32.tf32.tf32.f32 "
        "{%0,%1,%2,%3}, {%4,%5,%6,%7}, {%8,%9}, {%0,%1,%2,%3};\n"
        : "+f"(c[0]), "+f"(c[1]), "+f"(c[2]), "+f"(c[3])
        : "r"(a[0]), "r"(a[1]), "r"(a[2]), "r"(a[3]), "r"(b[0]), "r"(b[1]));
}

__device__ __forceinline__ void cp16(uint32_t s, const void* g) {
    asm volatile("cp.async.cg.shared.global [%0], [%1], 16;\n" :: "r"(s), "l"(g) : "memory");
}

__device__ __forceinline__ void ldsm4(uint32_t& r0, uint32_t& r1, uint32_t& r2, uint32_t& r3,
                                      uint32_t addr) {
    asm volatile("ldmatrix.sync.aligned.m8n8.x4.shared.b16 {%0,%1,%2,%3}, [%4];"
                 : "=r"(r0), "=r"(r1), "=r"(r2), "=r"(r3) : "r"(addr));
}

// =================================================================================
// XB = X @ B^T via tf32 MMA split-K (m-offset for half-split).
// =================================================================================
#define XBM_AF   (128 * 36)
#define XBM_BF   (64 * 36)
#define XBM_STG  (XBM_AF + XBM_BF)
#define XBM_SMEM (3 * XBM_STG * 4)
#define XBM_KIT  16

__device__ __forceinline__ void xbm_load(uint32_t sb, int buf, int it,
                                         const float* Ag, const float* Bg, int tid) {
    int k0 = it << 5;
    uint32_t sA = sb + (uint32_t)buf * (XBM_STG * 4);
    uint32_t sB = sA + XBM_AF * 4;
#pragma unroll
    for (int i = 0; i < 8; i++) {
        int idx = tid + (i << 7);
        int r = idx >> 3, c4 = (idx & 7) << 2;
        cp16(sA + (uint32_t)(r * 36 + c4) * 4u, Ag + (size_t)r * IN_F + k0 + c4);
    }
#pragma unroll
    for (int i = 0; i < 4; i++) {
        int idx = tid + (i << 7);
        int r = idx >> 3, c4 = (idx & 7) << 2;
        cp16(sB + (uint32_t)(r * 36 + c4) * 4u, Bg + (size_t)r * IN_F + k0 + c4);
    }
    asm volatile("cp.async.commit_group;\n" ::: "memory");
}

__global__ void __launch_bounds__(128, 2) xb_mma(const float* __restrict__ B, int bm0) {
    extern __shared__ float sm[];
    uint32_t sb = (uint32_t)__cvta_generic_to_shared(sm);
    int tid = threadIdx.x;
    int lane = tid & 31, wid = tid >> 5;
    int g = lane >> 2, tg = lane & 3;
    int wm = wid << 5;

    int bm = blockIdx.x + bm0;
    int ks = blockIdx.y;
    const float* Ag = g_X + (size_t)bm * 128 * IN_F + (ks << 9);
    const float* Bg = B + (ks << 9);

    uint32_t aoff = ((uint32_t)(wm + (((lane >> 3) & 1) << 3) + (lane & 7)) * 36u
                     + (uint32_t)((lane >> 4) << 2)) * 4u;
    uint32_t boff = ((uint32_t)(((lane >> 4) << 3) + (lane & 7)) * 36u
                     + (uint32_t)(((lane >> 3) & 1) << 2)) * 4u;

    xbm_load(sb, 0, 0, Ag, Bg, tid);
    xbm_load(sb, 1, 1, Ag, Bg, tid);

    float acc[2][8][4];
#pragma unroll
    for (int a = 0; a < 2; a++)
#pragma unroll
        for (int b = 0; b < 8; b++)
#pragma unroll
            for (int c = 0; c < 4; c++) acc[a][b][c] = 0.f;

    for (int it = 0; it < XBM_KIT; it++) {
        int b = it % 3;
        if (it == XBM_KIT - 1) asm volatile("cp.async.wait_group 0;\n" ::: "memory");
        else                   asm volatile("cp.async.wait_group 1;\n" ::: "memory");
        __syncthreads();

        if (it + 2 < XBM_KIT) xbm_load(sb, (it + 2) % 3, it + 2, Ag, Bg, tid);

        uint32_t sAb = sb + (uint32_t)b * (XBM_STG * 4) + aoff;
        uint32_t sBb = sb + (uint32_t)b * (XBM_STG * 4) + XBM_AF * 4 + boff;
#pragma unroll
        for (int ksu = 0; ksu < 4; ksu++) {
            uint32_t af[2][4], bf[4][4];
#pragma unroll
            for (int mf = 0; mf < 2; mf++)
                ldsm4(af[mf][0], af[mf][1], af[mf][2], af[mf][3],
                      sAb + (uint32_t)(mf * 2304 + ksu * 32));
#pragma unroll
            for (int nfp = 0; nfp < 4; nfp++)
                ldsm4(bf[nfp][0], bf[nfp][1], bf[nfp][2], bf[nfp][3],
                      sBb + (uint32_t)(nfp * 2304 + ksu * 32));
#pragma unroll
            for (int mf = 0; mf < 2; mf++)
#pragma unroll
                for (int nf = 0; nf < 8; nf++)
                    mma_tf32(acc[mf][nf], af[mf], &bf[nf >> 1][(nf & 1) << 1]);
        }
    }

    const size_t S = (size_t)NTOK * RANK;
    int row0 = bm * 128 + wm + g;
    int col0 = tg << 1;
    float* dstb = g_XBp + (size_t)ks * S;
#pragma unroll
    for (int mf = 0; mf < 2; mf++) {
#pragma unroll
        for (int nf = 0; nf < 8; nf++) {
            int r = row0 + (mf << 4);
            int c = col0 + (nf << 3);
            float2 v0 = make_float2(acc[mf][nf][0], acc[mf][nf][1]);
            float2 v1 = make_float2(acc[mf][nf][2], acc[mf][nf][3]);
            *reinterpret_cast<float2*>(dstb + (size_t)r * RANK + c) = v0;
            *reinterpret_cast<float2*>(dstb + (size_t)(r + 8) * RANK + c) = v1;
        }
    }
}

__global__ void xb_reduce() {
    int i = blockIdx.x * 256 + threadIdx.x;
    const size_t S = (size_t)NTOK * RANK;
    float s = 0.f;
#pragma unroll
    for (int k = 0; k < 8; k++) s += g_XBp[(size_t)k * S + i];
    g_XB[i] = tf32r(s);
}

// ---------------- small HMMA tf32 GEMM (ABX, K=64): 128x128 tiles ----------------
__device__ __forceinline__ void load_tile(const float* g, int ldg, uint32_t sbase, int tid) {
    int r = tid >> 3;
    int c4 = (tid & 7) << 2;
#pragma unroll
    for (int i = 0; i < 4; i++) {
        int row = r + (i << 5);
        cp16(sbase + (uint32_t)(row * 36 + c4) * 4u, g + (size_t)row * ldg + c4);
    }
}

#define GEMM_TB (128 * 36)
#define GEMM_SMEM (4 * GEMM_TB * 4)

__global__ void __launch_bounds__(256, 2) gemm_nt(const float* __restrict__ A,
                                                  const float* __restrict__ Bm,
                                                  float* __restrict__ C, int K) {
    extern __shared__ float sm[];
    uint32_t sA = (uint32_t)__cvta_generic_to_shared(sm);
    uint32_t sB = sA + 2u * GEMM_TB * 4u;
    int tid = threadIdx.x;
    const float* Ag = A + (size_t)(blockIdx.y * 128) * K;
    const float* Bg = Bm + (size_t)(blockIdx.x * 128) * K;
    int KIT = K >> 5;

    load_tile(Ag, K, sA, tid);
    load_tile(Bg, K, sB, tid);
    asm volatile("cp.async.commit_group;\n" ::: "memory");

    int lane = tid & 31, wid = tid >> 5;
    int g = lane >> 2, tg = lane & 3;
    int wm = (wid & 1) << 6;
    int wn = (wid >> 1) << 5;

    float acc[4][4][4];
#pragma unroll
    for (int a = 0; a < 4; a++)
#pragma unroll
        for (int b = 0; b < 4; b++)
#pragma unroll
            for (int c = 0; c < 4; c++) acc[a][b][c] = 0.f;

    const float* As = sm;
    const float* Bs = sm + 2 * GEMM_TB;

    for (int it = 0; it < KIT; it++) {
        if (it + 1 < KIT) {
            uint32_t nb = ((it + 1) & 1) ? (uint32_t)(GEMM_TB * 4) : 0u;
            load_tile(Ag + (it + 1) * 32, K, sA + nb, tid);
            load_tile(Bg + (it + 1) * 32, K, sB + nb, tid);
            asm volatile("cp.async.commit_group;\n" ::: "memory");
            asm volatile("cp.async.wait_group 1;\n" ::: "memory");
        } else {
            asm volatile("cp.async.wait_group 0;\n" ::: "memory");
        }
        __syncthreads();
        const float* Ac = As + (it & 1) * GEMM_TB;
        const float* Bc = Bs + (it & 1) * GEMM_TB;
#pragma unroll
        for (int ksu = 0; ksu < 4; ksu++) {
            int kc = ksu << 3;
            uint32_t af[4][4], bf[4][2];
#pragma unroll
            for (int mf = 0; mf < 4; mf++) {
                int r0 = wm + (mf << 4) + g;
                af[mf][0] = __float_as_uint(Ac[r0 * 36 + kc + tg]);
                af[mf][1] = __float_as_uint(Ac[(r0 + 8) * 36 + kc + tg]);
                af[mf][2] = __float_as_uint(Ac[r0 * 36 + kc + tg + 4]);
                af[mf][3] = __float_as_uint(Ac[(r0 + 8) * 36 + kc + tg + 4]);
            }
#pragma unroll
            for (int nf = 0; nf < 4; nf++) {
                int n0 = wn + (nf << 3) + g;
                bf[nf][0] = __float_as_uint(Bc[n0 * 36 + kc + tg]);
                bf[nf][1] = __float_as_uint(Bc[n0 * 36 + kc + tg + 4]);
            }
#pragma unroll
            for (int mf = 0; mf < 4; mf++)
#pragma unroll
                for (int nf = 0; nf < 4; nf++)
                    mma_tf32(acc[mf][nf], af[mf], bf[nf]);
        }
        __syncthreads();
    }

    int row0 = (blockIdx.y << 7) + wm + g;
    int col0 = (blockIdx.x << 7) + wn + (tg << 1);
#pragma unroll
    for (int mf = 0; mf < 4; mf++) {
#pragma unroll
        for (int nf = 0; nf < 4; nf++) {
            size_t r = (size_t)(row0 + (mf << 4));
            int c = col0 + (nf << 3);
            float2 v0 = make_float2(acc[mf][nf][0], acc[mf][nf][1]);
            float2 v1 = make_float2(acc[mf][nf][2], acc[mf][nf][3]);
            *reinterpret_cast<float2*>(C + r * 4096 + c) = v0;
            *reinterpret_cast<float2*>(C + (r + 8) * 4096 + c) = v1;
        }
    }
}

// =================================================================================
// Big HMMA tf32 GEMM (y-offset for half-split): exact R10 inner config.
// =================================================================================
#define Z2_TF   (128 * 36)
#define Z2_STG  (2 * Z2_TF)
#define Z2_SMEM (3 * Z2_STG * 4)
#define Z2_KIT  128

__device__ __forceinline__ void z2_load(uint32_t sb, int buf, int it,
                                        const float* Ag, const float* Bg, int tid) {
    int k0 = it << 5;
    uint32_t sA = sb + (uint32_t)buf * (Z2_STG * 4);
    uint32_t sB = sA + Z2_TF * 4;
#pragma unroll
    for (int i = 0; i < 8; i++) {
        int idx = tid + (i << 7);
        int r = idx >> 3, c4 = (idx & 7) << 2;
        cp16(sA + (uint32_t)(r * 36 + c4) * 4u, Ag + (size_t)r * IN_F + k0 + c4);
    }
#pragma unroll
    for (int i = 0; i < 8; i++) {
        int idx = tid + (i << 7);
        int r = idx >> 3, c4 = (idx & 7) << 2;
        cp16(sB + (uint32_t)(r * 36 + c4) * 4u, Bg + (size_t)r * IN_F + k0 + c4);
    }
    asm volatile("cp.async.commit_group;\n" ::: "memory");
}

__global__ void __launch_bounds__(128, 2) zgemm_big(const float* __restrict__ Xg,
                                                    const float* __restrict__ Wg,
                                                    float* __restrict__ Zg, int y0) {
    extern __shared__ float sm[];
    uint32_t sb = (uint32_t)__cvta_generic_to_shared(sm);
    int tid = threadIdx.x;
    int lane = tid & 31, wid = tid >> 5;
    int g = lane >> 2, tg = lane & 3;
    int wm = (wid & 1) << 6;
    int wn = (wid >> 1) << 6;

    int by = blockIdx.y + y0;
    const float* Ag = Xg + (size_t)by * 128 * IN_F;
    const float* Bg = Wg + (size_t)blockIdx.x * 128 * IN_F;

    uint32_t aoff = ((uint32_t)(wm + (((lane >> 3) & 1) << 3) + (lane & 7)) * 36u
                     + (uint32_t)((lane >> 4) << 2)) * 4u;
    uint32_t boff = ((uint32_t)(wn + ((lane >> 4) << 3) + (lane & 7)) * 36u
                     + (uint32_t)(((lane >> 3) & 1) << 2)) * 4u;

    z2_load(sb, 0, 0, Ag, Bg, tid);
    z2_load(sb, 1, 1, Ag, Bg, tid);

    float acc[4][8][4];
#pragma unroll
    for (int a = 0; a < 4; a++)
#pragma unroll
        for (int b = 0; b < 8; b++)
#pragma unroll
            for (int c = 0; c < 4; c++) acc[a][b][c] = 0.f;

    for (int it = 0; it < Z2_KIT; it++) {
        int b = it % 3;
        if (it == Z2_KIT - 1) asm volatile("cp.async.wait_group 0;\n" ::: "memory");
        else                  asm volatile("cp.async.wait_group 1;\n" ::: "memory");
        __syncthreads();

        if (it + 2 < Z2_KIT) z2_load(sb, (it + 2) % 3, it + 2, Ag, Bg, tid);

        uint32_t sAb = sb + (uint32_t)b * (Z2_STG * 4) + aoff;
        uint32_t sBb = sb + (uint32_t)b * (Z2_STG * 4) + Z2_TF * 4 + boff;
#pragma unroll
        for (int ksu = 0; ksu < 4; ksu++) {
            uint32_t af[4][4], bf[4][4];
#pragma unroll
            for (int mf = 0; mf < 4; mf++)
                ldsm4(af[mf][0], af[mf][1], af[mf][2], af[mf][3],
                      sAb + (uint32_t)(mf * 2304 + ksu * 32));
#pragma unroll
            for (int nfp = 0; nfp < 4; nfp++)
                ldsm4(bf[nfp][0], bf[nfp][1], bf[nfp][2], bf[nfp][3],
                      sBb + (uint32_t)(nfp * 2304 + ksu * 32));
#pragma unroll
            for (int mf = 0; mf < 4; mf++)
#pragma unroll
                for (int nf = 0; nf < 8; nf++)
                    mma_tf32(acc[mf][nf], af[mf], &bf[nf >> 1][(nf & 1) << 1]);
        }
    }

    int row0 = (by << 7) + wm + g;
    int col0 = (blockIdx.x << 7) + wn + (tg << 1);
#pragma unroll
    for (int mf = 0; mf < 4; mf++) {
#pragma unroll
        for (int nf = 0; nf < 8; nf++) {
            size_t r = (size_t)(row0 + (mf << 4));
            int c = col0 + (nf << 3);
            float2 v0 = make_float2(acc[mf][nf][0], acc[mf][nf][1]);
            float2 v1 = make_float2(acc[mf][nf][2], acc[mf][nf][3]);
            *reinterpret_cast<float2*>(Zg + r * 4096 + c) = v0;
            *reinterpret_cast<float2*>(Zg + (r + 8) * 4096 + c) = v1;
        }
    }
}

// ---------------- launch ----------------
extern "C" void kernel_launch(void* const* d_in, const int* in_sizes, int n_in,
                              void* d_out, int out_size) {
    const float* input   = (const float*)d_in[0];
    const int*   Qidxs   = (const int*)d_in[1];
    const float* cb      = (const float*)d_in[2];
    const float* SU      = (const float*)d_in[3];
    const float* SV      = (const float*)d_in[4];
    const float* A       = (const float*)d_in[5];
    const float* B       = (const float*)d_in[6];
    const float* scaleWH = (const float*)d_in[7];
    const float* bias    = (const float*)d_in[8];
    float* out = (float*)d_out;

    static bool attr_done = false;
    if (!attr_done) {
        bool ok1 = cudaFuncSetAttribute(gemm_nt, cudaFuncAttributeMaxDynamicSharedMemorySize,
                                        GEMM_SMEM) == cudaSuccess;
        bool ok2 = cudaFuncSetAttribute(zgemm_big, cudaFuncAttributeMaxDynamicSharedMemorySize,
                                        Z2_SMEM) == cudaSuccess;
        bool ok3 = cudaFuncSetAttribute(xb_mma, cudaFuncAttributeMaxDynamicSharedMemorySize,
                                        XBM_SMEM) == cudaSuccess;
        if (ok1 && ok2 && ok3) attr_done = true;
    }

    static float *X = nullptr, *W = nullptr, *Z = nullptr, *ABX = nullptr,
                 *XB = nullptr, *AQ = nullptr;
    if (!X) {
        cudaGetSymbolAddress((void**)&X,   g_X);
        cudaGetSymbolAddress((void**)&W,   g_W);
        cudaGetSymbolAddress((void**)&Z,   g_Z);
        cudaGetSymbolAddress((void**)&ABX, g_ABX);
        cudaGetSymbolAddress((void**)&XB,  g_XB);
        cudaGetSymbolAddress((void**)&AQ,  g_AQ);
    }

    static cudaStream_t s1 = nullptr, s2 = nullptr;
    static cudaEvent_t ev0, evc1, evA1, evA2, evD, evC, evZ1, evP1;
    static int streams_ok = -1;
    if (streams_ok < 0) {
        bool ok = cudaStreamCreateWithFlags(&s1, cudaStreamNonBlocking) == cudaSuccess;
        ok = ok && cudaStreamCreateWithFlags(&s2, cudaStreamNonBlocking) == cudaSuccess;
        ok = ok && cudaEventCreateWithFlags(&ev0,  cudaEventDisableTiming) == cudaSuccess;
        ok = ok && cudaEventCreateWithFlags(&evc1, cudaEventDisableTiming) == cudaSuccess;
        ok = ok && cudaEventCreateWithFlags(&evA1, cudaEventDisableTiming) == cudaSuccess;
        ok = ok && cudaEventCreateWithFlags(&evA2, cudaEventDisableTiming) == cudaSuccess;
        ok = ok && cudaEventCreateWithFlags(&evD,  cudaEventDisableTiming) == cudaSuccess;
        ok = ok && cudaEventCreateWithFlags(&evC,  cudaEventDisableTiming) == cudaSuccess;
        ok = ok && cudaEventCreateWithFlags(&evZ1, cudaEventDisableTiming) == cudaSuccess;
        ok = ok && cudaEventCreateWithFlags(&evP1, cudaEventDisableTiming) == cudaSuccess;
        streams_ok = ok ? 1 : 0;
    }

    if (streams_ok == 1) {
        cudaEventRecord(ev0, 0);
        cudaStreamWaitEvent(s1, ev0, 0);
        // s1: weight-side prep (independent of input FWHT)
        dequant_kernel<<<(OUT_F * (IN_F / 8)) / 256, 256, 0, s1>>>(Qidxs, cb);
        round_a_kernel<<<(OUT_F * RANK) / 256, 256, 0, s1>>>(A);
        cudaEventRecord(evD, s1);
        // s0: c1, then pre(h1); s2 runs pre(h2) concurrently with zgemm(h1)
        c1_kernel<<<16, 256>>>(SU, scaleWH);
        cudaEventRecord(evc1, 0);
        cudaStreamWaitEvent(s2, evc1, 0);
        fwht_pre<<<NTOK / 2, 256>>>(input, 0);
        cudaEventRecord(evA1, 0);
        fwht_pre<<<NTOK / 2, 256, 0, s2>>>(input, NTOK / 2);
        cudaEventRecord(evA2, s2);
        // s0: zgemm h1 (X h1 in-order, W via evD)
        cudaStreamWaitEvent(0, evD, 0);
        zgemm_big<<<dim3(32, 32), 128, Z2_SMEM>>>(X, W, Z, 0);
        cudaEventRecord(evZ1, 0);
        // s1: xb chain (halves gated on X halves), gemm_nt -> ABX
        cudaStreamWaitEvent(s1, evA1, 0);
        xb_mma<<<dim3(32, 8), 128, XBM_SMEM, s1>>>(B, 0);
        cudaStreamWaitEvent(s1, evA2, 0);
        xb_mma<<<dim3(32, 8), 128, XBM_SMEM, s1>>>(B, 32);
        xb_reduce<<<(NTOK * RANK) / 256, 256, 0, s1>>>();
        gemm_nt<<<dim3(32, 64), 256, GEMM_SMEM, s1>>>(XB, AQ, ABX, RANK);
        cudaEventRecord(evC, s1);
        // s0: zgemm h2 (X h2 via evA2)
        cudaStreamWaitEvent(0, evA2, 0);
        zgemm_big<<<dim3(32, 32), 128, Z2_SMEM>>>(X, W, Z, 32);
        // s2: post(h1) under zgemm(h2): needs Z h1 (evZ1) + ABX (evC)
        cudaStreamWaitEvent(s2, evZ1, 0);
        cudaStreamWaitEvent(s2, evC, 0);
        fwht_post<<<NTOK / 2, 256, 0, s2>>>(SV, bias, out, 0);
        cudaEventRecord(evP1, s2);
        // s0: post(h2) after zgemm h2 (in-order) + ABX (evC); then join s2
        cudaStreamWaitEvent(0, evC, 0);
        fwht_post<<<NTOK / 2, 256>>>(SV, bias, out, NTOK / 2);
        cudaStreamWaitEvent(0, evP1, 0);
    } else {
        c1_kernel<<<16, 256>>>(SU, scaleWH);
        fwht_pre<<<NTOK / 2, 256>>>(input, 0);
        fwht_pre<<<NTOK / 2, 256>>>(input, NTOK / 2);
        dequant_kernel<<<(OUT_F * (IN_F / 8)) / 256, 256>>>(Qidxs, cb);
        zgemm_big<<<dim3(32, 32), 128, Z2_SMEM>>>(X, W, Z, 0);
        zgemm_big<<<dim3(32, 32), 128, Z2_SMEM>>>(X, W, Z, 32);
        round_a_kernel<<<(OUT_F * RANK) / 256, 256>>>(A);
        xb_mma<<<dim3(32, 8), 128, XBM_SMEM>>>(B, 0);
        xb_mma<<<dim3(32, 8), 128, XBM_SMEM>>>(B, 32);
        xb_reduce<<<(NTOK * RANK) / 256, 256>>>();
        gemm_nt<<<dim3(32, 64), 256, GEMM_SMEM>>>(XB, AQ, ABX, RANK);
        fwht_post<<<NTOK / 2, 256>>>(SV, bias, out, 0);
        fwht_post<<<NTOK / 2, 256>>>(SV, bias, out, NTOK / 2);
    }
}